// round 2
// baseline (speedup 1.0000x reference)
#include <cuda_runtime.h>
#include <stdint.h>
#include <math.h>

// Packed dual-FMA (Blackwell f32x2). acc.lo += a.lo*b.lo ; acc.hi += a.hi*b.hi
#define FFMA2(acc, a, b) \
    asm volatile("fma.rn.f32x2 %0, %1, %2, %0;" : "+l"(acc) : "l"(a), "l"(b))

// Composed nope matrix: out_nope[o] = sum_kk B_mat[o*1024+kk] * x[g=kk>>7, dfull=kk&127]
__device__ float B_mat[64 * 1024];

// ---------------------------------------------------------------------------
// Build B[o][g*128+dfull] = sum_{r=1..15} W[o, part*480 + n2*15 + r-1] * qk_w[n2, p*8+g, r]
// dfull -> (part = dfull>>6, d = dfull&63, f = d&1, p = (d>>1)&1, m = d>>2, n2 = f*16+m)
// ---------------------------------------------------------------------------
__global__ __launch_bounds__(1024) void build_B_kernel(
    const float* __restrict__ qk_w,   // [32][16][16]
    const float* __restrict__ W)      // [64][960]
{
    int t = blockIdx.x * blockDim.x + threadIdx.x;   // 65536 total
    int o = t >> 10;
    int kk = t & 1023;
    int g = kk >> 7;
    int dfull = kk & 127;
    int part = dfull >> 6;
    int d = dfull & 63;
    int f = d & 1;
    int p = (d >> 1) & 1;
    int m = d >> 2;
    int n2 = f * 16 + m;
    const float* wrow = W + o * 960 + part * 480 + n2 * 15;
    const float* qrow = qk_w + n2 * 256 + (p * 8 + g) * 16;
    float acc = 0.f;
#pragma unroll
    for (int r = 1; r < 16; ++r)
        acc += wrow[r - 1] * qrow[r];
    B_mat[t] = acc;
}

// ---------------------------------------------------------------------------
// Rope path: per token, 256 q-rope outputs + 64 k-rope outputs, each a
// 16-tap weighted gather with weights qk_w[:, :, 0]. One block per token.
// ---------------------------------------------------------------------------
__global__ __launch_bounds__(256) void rope_kernel(
    const float* __restrict__ q,      // [N,32,128]
    const float* __restrict__ k,      // [N,8,128]
    const float* __restrict__ qk_w,   // [32,16,16]
    float* __restrict__ out, int N)
{
    __shared__ float q_s[4096];
    __shared__ float k_s[1024];
    __shared__ float w0t[512];        // [c][n2] transposed for conflict-free reads
    const int b = blockIdx.x;
    const int t = threadIdx.x;

    const float4* qg = (const float4*)(q + (size_t)b * 4096);
    float4* qs4 = (float4*)q_s;
#pragma unroll
    for (int i = 0; i < 4; ++i) qs4[t + 256 * i] = qg[t + 256 * i];
    ((float4*)k_s)[t] = ((const float4*)(k + (size_t)b * 1024))[t];
#pragma unroll
    for (int i = 0; i < 2; ++i) {
        int idx = t + 256 * i;            // idx = c*32 + n2
        int c = idx >> 5, n2 = idx & 31;
        w0t[idx] = qk_w[n2 * 256 + c * 16];   // r = 0
    }
    __syncthreads();

    // q-rope: t -> (j = t>>6, part = (t>>5)&1, n2 = t&31)
    {
        const int j = t >> 6, part = (t >> 5) & 1, n2 = t & 31;
        const int dbase = ((n2 & 15) << 2) + (n2 >> 4) + (part << 6);
        float acc = 0.f;
#pragma unroll
        for (int c = 0; c < 16; ++c) {
            int g = c & 7, p = c >> 3;
            acc += w0t[c * 32 + n2] * q_s[((g << 2) + j) * 128 + dbase + (p << 1)];
        }
        out[(size_t)b * 512 + j * 128 + part * 32 + n2] = acc;
    }
    // k-rope: first 64 threads
    if (t < 64) {
        const int part = t >> 5, n2 = t & 31;
        const int dbase = ((n2 & 15) << 2) + (n2 >> 4) + (part << 6);
        float acc = 0.f;
#pragma unroll
        for (int c = 0; c < 16; ++c) {
            int g = c & 7, p = c >> 3;
            acc += w0t[c * 32 + n2] * k_s[(g << 7) + dbase + (p << 1)];
        }
        out[(size_t)N * 512 + (size_t)b * 128 + part * 32 + n2] = acc;
    }
}

// ---------------------------------------------------------------------------
// Nope GEMM: out[row, o] = sum_{kk<1024} A[row,kk] * B_mat[o,kk]
// IS_Q: rows = (token, j) (16 tokens -> 64 rows/block), A strided per g chunk.
// else: rows = tokens (64/block), A contiguous.
// 64x64 output tile, K chunked by 128 through smem, 4x4 thread tile,
// K-pairs accumulated with packed f32x2 FMA.
// ---------------------------------------------------------------------------
template <bool IS_Q>
__global__ __launch_bounds__(256) void nope_gemm_kernel(
    const float* __restrict__ X, float* __restrict__ out, int N)
{
    extern __shared__ float sm[];
    float* A_sh = sm;                 // [64][132] (pad 4 -> 16B-aligned rows)
    float* B_sh = sm + 64 * 132;      // [64][132]
    const int tid = threadIdx.x;
    const int tx = tid & 15, ty = tid >> 4;
    const int lrow = tid >> 2, lq = tid & 3;

    const float* asrc;
    if (IS_Q) {
        int b0 = blockIdx.x * 16;
        asrc = X + (size_t)(b0 + (lrow >> 2)) * 4096 + (lrow & 3) * 128;
    } else {
        int b0 = blockIdx.x * 64;
        asrc = X + (size_t)(b0 + lrow) * 1024;
    }
    const float* bsrc = B_mat + lrow * 1024;

    unsigned long long acc[4][4];
#pragma unroll
    for (int r = 0; r < 4; ++r)
#pragma unroll
        for (int c = 0; c < 4; ++c) acc[r][c] = 0ull;

    for (int g = 0; g < 8; ++g) {
        const float4* a4 = (const float4*)(asrc + g * (IS_Q ? 512 : 128));
        const float4* b4 = (const float4*)(bsrc + g * 128);
        float4* As = (float4*)(A_sh + lrow * 132);
        float4* Bs = (float4*)(B_sh + lrow * 132);
#pragma unroll
        for (int i = 0; i < 8; ++i) {
            As[lq + 4 * i] = a4[lq + 4 * i];
            Bs[lq + 4 * i] = b4[lq + 4 * i];
        }
        __syncthreads();
        const float* Ap = A_sh + ty * 132;   // rows ty + 16*r
        const float* Bp = B_sh + tx * 132;   // cols tx + 16*c
#pragma unroll 8
        for (int kk = 0; kk < 128; kk += 2) {
            unsigned long long a[4], bb[4];
#pragma unroll
            for (int r = 0; r < 4; ++r)
                a[r] = *(const unsigned long long*)(Ap + r * (16 * 132) + kk);
#pragma unroll
            for (int c = 0; c < 4; ++c)
                bb[c] = *(const unsigned long long*)(Bp + c * (16 * 132) + kk);
#pragma unroll
            for (int r = 0; r < 4; ++r)
#pragma unroll
                for (int c = 0; c < 4; ++c) FFMA2(acc[r][c], a[r], bb[c]);
        }
        __syncthreads();
    }

#pragma unroll
    for (int r = 0; r < 4; ++r) {
        int row = ty + 16 * r;
#pragma unroll
        for (int c = 0; c < 4; ++c) {
            int o = tx + 16 * c;
            float lo = __uint_as_float((unsigned)(acc[r][c] & 0xffffffffull));
            float hi = __uint_as_float((unsigned)(acc[r][c] >> 32));
            float val = lo + hi;
            if (IS_Q) {
                int b = blockIdx.x * 16 + (row >> 2);
                out[(size_t)b * 512 + (row & 3) * 128 + 64 + o] = val;
            } else {
                int b = blockIdx.x * 64 + row;
                out[(size_t)N * 512 + (size_t)b * 128 + 64 + o] = val;
            }
        }
    }
}

// ---------------------------------------------------------------------------
// Weights: weights[b,j] = || concat_g ( v[b,g] @ vt[g*4+j] ) ||_2
// vt (64KB) staged once per block in smem, transposed to [d][h*4+s] for
// conflict-free reads; 16 tokens per block (2 per iteration across 256 thr).
// ---------------------------------------------------------------------------
__global__ __launch_bounds__(256) void weights_kernel(
    const float* __restrict__ v,      // [N,8,128]
    const float* __restrict__ vt,     // [32,128,4]
    float* __restrict__ out, int N)
{
    extern __shared__ float sm[];
    float* vt_s = sm;                  // [128 d][128 (h*4+s)]
    float* v_s  = sm + 16384;          // [2][1024]
    float* red  = sm + 16384 + 2048;   // [2][128]
    const int tid = threadIdx.x;

    for (int i = tid; i < 16384; i += 256) {
        int h = i >> 9, d = (i >> 2) & 127, s = i & 3;
        vt_s[d * 128 + h * 4 + s] = vt[i];
    }
    const int half = tid >> 7, t = tid & 127;   // t = h*4+s
    const int g = t >> 4;                        // h>>2
    const int b0 = blockIdx.x * 16;
    __syncthreads();

    for (int it = 0; it < 8; ++it) {
        int b = b0 + it * 2;
        const float4* vg = (const float4*)(v + (size_t)b * 1024);
        ((float4*)v_s)[tid] = vg[tid];
        ((float4*)v_s)[tid + 256] = vg[tid + 256];
        __syncthreads();
        const float* vrow = v_s + half * 1024 + g * 128;
        const float* vtp = vt_s + t;
        float a = 0.f;
#pragma unroll 8
        for (int d = 0; d < 128; ++d) a += vrow[d] * vtp[d * 128];
        red[half * 128 + t] = a * a;
        __syncthreads();
        if (t < 4) {
            float sum = 0.f;
#pragma unroll
            for (int g2 = 0; g2 < 8; ++g2)
#pragma unroll
                for (int s2 = 0; s2 < 4; ++s2)
                    sum += red[half * 128 + g2 * 16 + t * 4 + s2];
            out[(size_t)N * 512 + (size_t)N * 128 + (size_t)(b + half) * 4 + t] = sqrtf(sum);
        }
        __syncthreads();
    }
}

// ---------------------------------------------------------------------------
extern "C" void kernel_launch(void* const* d_in, const int* in_sizes, int n_in,
                              void* d_out, int out_size)
{
    const float* q      = (const float*)d_in[0];
    const float* k      = (const float*)d_in[1];
    const float* v      = (const float*)d_in[2];
    const float* q_orig = (const float*)d_in[3];
    const float* k_orig = (const float*)d_in[4];
    const float* qk_w   = (const float*)d_in[5];
    const float* W      = (const float*)d_in[6];
    const float* vt     = (const float*)d_in[7];
    float* out = (float*)d_out;
    const int N = in_sizes[0] / (32 * 128);   // 8192

    const int gemm_smem = 2 * 64 * 132 * 4;           // 67584
    const int wts_smem  = (16384 + 2048 + 256) * 4;   // 74752
    cudaFuncSetAttribute(nope_gemm_kernel<true>,
                         cudaFuncAttributeMaxDynamicSharedMemorySize, gemm_smem);
    cudaFuncSetAttribute(nope_gemm_kernel<false>,
                         cudaFuncAttributeMaxDynamicSharedMemorySize, gemm_smem);
    cudaFuncSetAttribute(weights_kernel,
                         cudaFuncAttributeMaxDynamicSharedMemorySize, wts_smem);

    build_B_kernel<<<64, 1024>>>(qk_w, W);
    rope_kernel<<<N, 256>>>(q, k, qk_w, out, N);
    nope_gemm_kernel<true><<<N / 16, 256, gemm_smem>>>(q_orig, out, N);
    nope_gemm_kernel<false><<<N / 64, 256, gemm_smem>>>(k_orig, out, N);
    weights_kernel<<<N / 16, 256, wts_smem>>>(v, vt, out, N);
}

// round 5
// speedup vs baseline: 2.3595x; 2.3595x over previous
#include <cuda_runtime.h>
#include <stdint.h>
#include <math.h>

// ===========================================================================
// B_all[128][1024]: rows 0-63  = rope map  (out cols 0..63)
//                   rows 64-127= composed nope map (out cols 64..127)
// Pre-rounded to tf32 (rna).
// ===========================================================================
__device__ float B_all[128 * 1024];

__device__ __forceinline__ float to_tf32(float x) {
    float r; asm("cvt.rna.tf32.f32 %0, %1;" : "=f"(r) : "f"(x)); return r;
}
__device__ __forceinline__ uint32_t tf32_bits(float x) {
    float r; asm("cvt.rna.tf32.f32 %0, %1;" : "=f"(r) : "f"(x));
    return __float_as_uint(r);
}
__device__ __forceinline__ uint32_t smem_u32(const void* p) {
    uint32_t a;
    asm("{ .reg .u64 t; cvta.to.shared.u64 t, %1; cvt.u32.u64 %0, t; }" : "=r"(a) : "l"(p));
    return a;
}
__device__ __forceinline__ void cp_async16(uint32_t dst, const void* src) {
    asm volatile("cp.async.cg.shared.global [%0], [%1], 16;"
                 :: "r"(dst), "l"(src) : "memory");
}
#define CP_COMMIT() asm volatile("cp.async.commit_group;" ::: "memory")

#define MMA_TF32(c, a, b) \
    asm volatile( \
        "mma.sync.aligned.m16n8k8.row.col.f32.tf32.tf32.f32 " \
        "{%0,%1,%2,%3}, {%4,%5,%6,%7}, {%8,%9}, {%0,%1,%2,%3};" \
        : "+f"((c)[0]), "+f"((c)[1]), "+f"((c)[2]), "+f"((c)[3]) \
        : "r"((a)[0]), "r"((a)[1]), "r"((a)[2]), "r"((a)[3]), \
          "r"((b)[0]), "r"((b)[1]))

// ---------------------------------------------------------------------------
// Build B_all. 131072 threads.
// ---------------------------------------------------------------------------
__global__ __launch_bounds__(1024) void build_B_kernel(
    const float* __restrict__ qk_w,   // [32][16][16]
    const float* __restrict__ W)      // [64][960]
{
    int t = blockIdx.x * blockDim.x + threadIdx.x;   // 131072 total
    int o = t >> 10;
    int kk = t & 1023;
    int g = kk >> 7;
    int dfull = kk & 127;
    float acc = 0.f;
    if (o < 64) {
        int part = o >> 5, n2 = o & 31;
        int dbase = ((n2 & 15) << 2) + (n2 >> 4) + (part << 6);
#pragma unroll
        for (int p = 0; p < 2; ++p)
            if (dfull == dbase + 2 * p)
                acc += qk_w[n2 * 256 + (p * 8 + g) * 16];
    } else {
        int oo = o - 64;
        int part = dfull >> 6;
        int d = dfull & 63;
        int f = d & 1, p = (d >> 1) & 1, m = d >> 2;
        int n2 = f * 16 + m;
        const float* wrow = W + oo * 960 + part * 480 + n2 * 15;
        const float* qrow = qk_w + n2 * 256 + (p * 8 + g) * 16;
#pragma unroll
        for (int r = 1; r < 16; ++r)
            acc += wrow[r - 1] * qrow[r];
    }
    B_all[t] = to_tf32(acc);
}

// ---------------------------------------------------------------------------
// Fused GEMM (tf32 mma.sync): 640 blocks x [128 rows x 64 cols], K=1024.
//  blk [0,256)   : A = q       (rows (b,j)),  B rows 0..63,  out cols 0..63
//  blk [256,320) : A = k       (rows b),      B rows 0..63,  out cols 0..63
//  blk [320,576) : A = q_orig  (rows (b,j)),  B rows 64..127,out cols 64..127
//  blk [576,640) : A = k_orig  (rows b),      B rows 64..127,out cols 64..127
// 8 warps tiled 4M x 2N (warp = 32 rows x 32 cols), K chunk = 32,
// 2-stage cp.async pipeline. smem rows padded to 36 floats (conflict-free).
// ---------------------------------------------------------------------------
static constexpr int A_STRIDE = 36;                 // floats
static constexpr int A_BYTES = 128 * A_STRIDE * 4;  // 18432
static constexpr int B_BYTES = 64 * A_STRIDE * 4;   // 9216
static constexpr int STAGE_BYTES = A_BYTES + B_BYTES;  // 27648
static constexpr int GEMM_SMEM = 2 * STAGE_BYTES;      // 55296

__global__ __launch_bounds__(256) void fused_gemm_kernel(
    const float* __restrict__ q, const float* __restrict__ k,
    const float* __restrict__ q_orig, const float* __restrict__ k_orig,
    float* __restrict__ out, int N)
{
    extern __shared__ float sm[];
    const uint32_t sbase = smem_u32(sm);

    const int tid = threadIdx.x;
    const int wid = tid >> 5;
    const int lane = tid & 31;
    const int gid = lane >> 2;      // group (row within fragment)
    const int tig = lane & 3;       // thread-in-group (k within fragment)
    const int wm = wid >> 1;        // 0..3 (M tile)
    const int wn = wid & 1;         // 0..1 (N tile)
    const int blk = blockIdx.x;

    const float* X;
    int row0, colOff, brow0;
    bool qrows;
    if (blk < 256)      { X = q;      row0 = blk * 128;         colOff = 0;  brow0 = 0;  qrows = true;  }
    else if (blk < 320) { X = k;      row0 = (blk - 256) * 128; colOff = 0;  brow0 = 0;  qrows = false; }
    else if (blk < 576) { X = q_orig; row0 = (blk - 320) * 128; colOff = 64; brow0 = 64; qrows = true;  }
    else                { X = k_orig; row0 = (blk - 576) * 128; colOff = 64; brow0 = 64; qrows = false; }

    // per-thread load assignments (A: 4 x 16B, B: 2 x 16B per stage)
    // A chunk it = tid + 256*i : row = it>>3, c4 = it&7
    // B chunk it = tid + 256*i : row = it>>3, c4 = it&7
    auto load_stage = [&](int s, int kc) {
        uint32_t abase = sbase + s * STAGE_BYTES;
        uint32_t bbase = abase + A_BYTES;
#pragma unroll
        for (int i = 0; i < 4; ++i) {
            int it = tid + 256 * i;
            int r = it >> 3, c4 = it & 7;
            const float* src;
            if (qrows) {
                int gr = row0 + r;
                src = X + (size_t)(gr >> 2) * 4096 + (size_t)(kc >> 2) * 512
                        + (size_t)(gr & 3) * 128 + (kc & 3) * 32 + c4 * 4;
            } else {
                src = X + (size_t)(row0 + r) * 1024 + kc * 32 + c4 * 4;
            }
            cp_async16(abase + (r * A_STRIDE + c4 * 4) * 4, src);
        }
#pragma unroll
        for (int i = 0; i < 2; ++i) {
            int it = tid + 256 * i;
            int r = it >> 3, c4 = it & 7;
            const float* src = B_all + (size_t)(brow0 + r) * 1024 + kc * 32 + c4 * 4;
            cp_async16(bbase + (r * A_STRIDE + c4 * 4) * 4, src);
        }
        CP_COMMIT();
    };

    float acc[2][4][4];
#pragma unroll
    for (int t = 0; t < 2; ++t)
#pragma unroll
        for (int n = 0; n < 4; ++n)
#pragma unroll
            for (int e = 0; e < 4; ++e) acc[t][n][e] = 0.f;

    load_stage(0, 0);

    for (int kc = 0; kc < 32; ++kc) {
        int s = kc & 1;
        if (kc + 1 < 32) {
            load_stage(s ^ 1, kc + 1);
            asm volatile("cp.async.wait_group 1;" ::: "memory");
        } else {
            asm volatile("cp.async.wait_group 0;" ::: "memory");
        }
        __syncthreads();

        const float* A_sh = sm + s * (STAGE_BYTES / 4);
        const float* B_sh = A_sh + (A_BYTES / 4);
#pragma unroll
        for (int k0 = 0; k0 < 32; k0 += 8) {
            uint32_t a[2][4];
#pragma unroll
            for (int t = 0; t < 2; ++t) {
                int ar = wm * 32 + t * 16;
                const float* p0 = A_sh + (ar + gid) * A_STRIDE + k0 + tig;
                const float* p1 = A_sh + (ar + gid + 8) * A_STRIDE + k0 + tig;
                a[t][0] = tf32_bits(p0[0]);
                a[t][1] = tf32_bits(p1[0]);
                a[t][2] = tf32_bits(p0[4]);
                a[t][3] = tf32_bits(p1[4]);
            }
            uint32_t b[4][2];
#pragma unroll
            for (int n = 0; n < 4; ++n) {
                int bc = wn * 32 + n * 8 + gid;
                const float* p = B_sh + bc * A_STRIDE + k0 + tig;
                b[n][0] = __float_as_uint(p[0]);
                b[n][1] = __float_as_uint(p[4]);
            }
#pragma unroll
            for (int t = 0; t < 2; ++t)
#pragma unroll
                for (int n = 0; n < 4; ++n)
                    MMA_TF32(acc[t][n], a[t], b[n]);
        }
        __syncthreads();
    }

    // epilogue
#pragma unroll
    for (int t = 0; t < 2; ++t) {
#pragma unroll
        for (int half = 0; half < 2; ++half) {
            int row = wm * 32 + t * 16 + gid + half * 8;
            int gr = row0 + row;
            float* op = qrows
                ? out + (size_t)(gr >> 2) * 512 + (size_t)(gr & 3) * 128 + colOff
                : out + (size_t)N * 512 + (size_t)gr * 128 + colOff;
#pragma unroll
            for (int n = 0; n < 4; ++n) {
                int col = wn * 32 + n * 8 + 2 * tig;
                float2 v;
                v.x = acc[t][n][half * 2 + 0];
                v.y = acc[t][n][half * 2 + 1];
                *(float2*)(op + col) = v;
            }
        }
    }
}

// ---------------------------------------------------------------------------
// Weights: weights[b,j] = || concat_g ( v[b,g] @ vt[g*4+j] ) ||_2
// ---------------------------------------------------------------------------
__global__ __launch_bounds__(256) void weights_kernel(
    const float* __restrict__ v,      // [N,8,128]
    const float* __restrict__ vt,     // [32,128,4]
    float* __restrict__ out, int N)
{
    extern __shared__ float smw[];
    float* vt_s = smw;                  // [128 d][128 (h*4+s)]
    float* v_s  = smw + 16384;          // [2][1024]
    float* red  = smw + 16384 + 2048;   // [2][128]
    const int tid = threadIdx.x;

    for (int i = tid; i < 16384; i += 256) {
        int h = i >> 9, d = (i >> 2) & 127, s = i & 3;
        vt_s[d * 128 + h * 4 + s] = vt[i];
    }
    const int half = tid >> 7, t = tid & 127;
    const int g = t >> 4;
    const int b0 = blockIdx.x * 16;
    __syncthreads();

    for (int it = 0; it < 8; ++it) {
        int b = b0 + it * 2;
        const float4* vg = (const float4*)(v + (size_t)b * 1024);
        ((float4*)v_s)[tid] = vg[tid];
        ((float4*)v_s)[tid + 256] = vg[tid + 256];
        __syncthreads();
        const float* vrow = v_s + half * 1024 + g * 128;
        const float* vtp = vt_s + t;
        float a = 0.f;
#pragma unroll 8
        for (int d = 0; d < 128; ++d) a += vrow[d] * vtp[d * 128];
        red[half * 128 + t] = a * a;
        __syncthreads();
        if (t < 4) {
            float sum = 0.f;
#pragma unroll
            for (int g2 = 0; g2 < 8; ++g2)
#pragma unroll
                for (int s2 = 0; s2 < 4; ++s2)
                    sum += red[half * 128 + g2 * 16 + t * 4 + s2];
            out[(size_t)N * 512 + (size_t)N * 128 + (size_t)(b + half) * 4 + t] = sqrtf(sum);
        }
        __syncthreads();
    }
}

// ---------------------------------------------------------------------------
extern "C" void kernel_launch(void* const* d_in, const int* in_sizes, int n_in,
                              void* d_out, int out_size)
{
    const float* q      = (const float*)d_in[0];
    const float* k      = (const float*)d_in[1];
    const float* v      = (const float*)d_in[2];
    const float* q_orig = (const float*)d_in[3];
    const float* k_orig = (const float*)d_in[4];
    const float* qk_w   = (const float*)d_in[5];
    const float* W      = (const float*)d_in[6];
    const float* vt     = (const float*)d_in[7];
    float* out = (float*)d_out;
    const int N = in_sizes[0] / (32 * 128);   // 8192

    const int wts_smem = (16384 + 2048 + 256) * 4;   // 74752
    cudaFuncSetAttribute(fused_gemm_kernel,
                         cudaFuncAttributeMaxDynamicSharedMemorySize, GEMM_SMEM);
    cudaFuncSetAttribute(weights_kernel,
                         cudaFuncAttributeMaxDynamicSharedMemorySize, wts_smem);

    build_B_kernel<<<128, 1024>>>(qk_w, W);
    fused_gemm_kernel<<<640, 256, GEMM_SMEM>>>(q, k, q_orig, k_orig, out, N);
    weights_kernel<<<N / 16, 256, wts_smem>>>(v, vt, out, N);
}

// round 7
// speedup vs baseline: 3.1762x; 1.3461x over previous
#include <cuda_runtime.h>
#include <stdint.h>
#include <math.h>

// ===========================================================================
// B_all[192][1024]:
//   rows 0..63    composed nope map  (index cols 64..127)
//   rows 64..191  expanded v-weights map (scratch cols 0..127, block-diagonal)
// Pre-rounded to tf32 (rna).
// w_scratch[N][128]: per-token w values (j,g,r) before norm reduction.
// ===========================================================================
__device__ float B_all[192 * 1024];
__device__ float w_scratch[8192 * 128];

__device__ __forceinline__ float to_tf32(float x) {
    float r; asm("cvt.rna.tf32.f32 %0, %1;" : "=f"(r) : "f"(x)); return r;
}
__device__ __forceinline__ uint32_t tf32_bits(float x) {
    float r; asm("cvt.rna.tf32.f32 %0, %1;" : "=f"(r) : "f"(x));
    return __float_as_uint(r);
}
__device__ __forceinline__ uint32_t smem_u32(const void* p) {
    uint32_t a;
    asm("{ .reg .u64 t; cvta.to.shared.u64 t, %1; cvt.u32.u64 %0, t; }" : "=r"(a) : "l"(p));
    return a;
}
__device__ __forceinline__ void cp_async16(uint32_t dst, const void* src) {
    asm volatile("cp.async.cg.shared.global [%0], [%1], 16;"
                 :: "r"(dst), "l"(src) : "memory");
}
#define CP_COMMIT() asm volatile("cp.async.commit_group;" ::: "memory")

#define MMA_TF32(c, a, b) \
    asm volatile( \
        "mma.sync.aligned.m16n8k8.row.col.f32.tf32.tf32.f32 " \
        "{%0,%1,%2,%3}, {%4,%5,%6,%7}, {%8,%9}, {%0,%1,%2,%3};" \
        : "+f"((c)[0]), "+f"((c)[1]), "+f"((c)[2]), "+f"((c)[3]) \
        : "r"((a)[0]), "r"((a)[1]), "r"((a)[2]), "r"((a)[3]), \
          "r"((b)[0]), "r"((b)[1]))

// ---------------------------------------------------------------------------
// Build B_all: 192 blocks (one output row each) x 1024 threads (one kk each).
// ---------------------------------------------------------------------------
__global__ __launch_bounds__(1024) void build_B_kernel(
    const float* __restrict__ qk_w,   // [32][16][16]
    const float* __restrict__ W,      // [64][960]
    const float* __restrict__ vt)     // [32][128][4]
{
    const int o = blockIdx.x;
    const int kk = threadIdx.x;
    const int g = kk >> 7;
    const int dfull = kk & 127;
    float acc = 0.f;
    if (o < 64) {
        // composed nope map
        int part = dfull >> 6;
        int d = dfull & 63;
        int f = d & 1, p = (d >> 1) & 1, m = d >> 2;
        int n2 = f * 16 + m;
        const float* wrow = W + o * 960 + part * 480 + n2 * 15;
        const float* qrow = qk_w + n2 * 256 + (p * 8 + g) * 16;
#pragma unroll
        for (int r = 1; r < 16; ++r)
            acc += wrow[r - 1] * qrow[r];
    } else {
        // v-weights map: cidx = o-64 = j*32 + gg*4 + r
        int cidx = o - 64;
        int j = cidx >> 5;
        int gg = (cidx >> 2) & 7;
        int r = cidx & 3;
        if (g == gg)
            acc = vt[(size_t)(gg * 4 + j) * 512 + dfull * 4 + r];
    }
    B_all[o * 1024 + kk] = to_tf32(acc);
}

// ---------------------------------------------------------------------------
// Rope path (scalar, DRAM-bound): per token, 256 q outputs + 64 k outputs,
// each a 16-tap weighted gather with weights qk_w[:, :, 0]. One block/token.
// ---------------------------------------------------------------------------
__global__ __launch_bounds__(256) void rope_kernel(
    const float* __restrict__ q,      // [N,32,128]
    const float* __restrict__ k,      // [N,8,128]
    const float* __restrict__ qk_w,   // [32,16,16]
    float* __restrict__ out, int N)
{
    __shared__ float q_s[4096];
    __shared__ float k_s[1024];
    __shared__ float w0t[512];        // [c][n2]
    const int b = blockIdx.x;
    const int t = threadIdx.x;

    const float4* qg = (const float4*)(q + (size_t)b * 4096);
    float4* qs4 = (float4*)q_s;
#pragma unroll
    for (int i = 0; i < 4; ++i) qs4[t + 256 * i] = qg[t + 256 * i];
    ((float4*)k_s)[t] = ((const float4*)(k + (size_t)b * 1024))[t];
#pragma unroll
    for (int i = 0; i < 2; ++i) {
        int idx = t + 256 * i;
        int c = idx >> 5, n2 = idx & 31;
        w0t[idx] = qk_w[n2 * 256 + c * 16];
    }
    __syncthreads();

    {
        const int j = t >> 6, part = (t >> 5) & 1, n2 = t & 31;
        const int dbase = ((n2 & 15) << 2) + (n2 >> 4) + (part << 6);
        float acc = 0.f;
#pragma unroll
        for (int c = 0; c < 16; ++c) {
            int g = c & 7, p = c >> 3;
            acc += w0t[c * 32 + n2] * q_s[((g << 2) + j) * 128 + dbase + (p << 1)];
        }
        out[(size_t)b * 512 + j * 128 + part * 32 + n2] = acc;
    }
    if (t < 64) {
        const int part = t >> 5, n2 = t & 31;
        const int dbase = ((n2 & 15) << 2) + (n2 >> 4) + (part << 6);
        float acc = 0.f;
#pragma unroll
        for (int c = 0; c < 16; ++c) {
            int g = c & 7, p = c >> 3;
            acc += w0t[c * 32 + n2] * k_s[(g << 7) + dbase + (p << 1)];
        }
        out[(size_t)N * 512 + (size_t)b * 128 + part * 32 + n2] = acc;
    }
}

// ---------------------------------------------------------------------------
// Fused GEMM (tf32 mma.sync): 448 blocks x [128 rows x 64 cols], K=1024.
//  blk [0,256)   : A = q_orig (rows (b,j)), B rows 0..63,  out cols 64..127
//  blk [256,320) : A = k_orig (rows b),     B rows 0..63,  out cols 64..127
//  blk [320,448) : A = v      (rows b),     B rows 64+64*h.., scratch cols 64*h..
// 8 warps tiled 4M x 2N, K chunk = 32, 2-stage cp.async pipeline.
// ---------------------------------------------------------------------------
static constexpr int A_STRIDE = 36;                 // floats
static constexpr int A_BYTES = 128 * A_STRIDE * 4;  // 18432
static constexpr int B_BYTES = 64 * A_STRIDE * 4;   // 9216
static constexpr int STAGE_BYTES = A_BYTES + B_BYTES;  // 27648
static constexpr int GEMM_SMEM = 2 * STAGE_BYTES;      // 55296

__global__ __launch_bounds__(256) void fused_gemm_kernel(
    const float* __restrict__ q_orig, const float* __restrict__ k_orig,
    const float* __restrict__ v,
    float* __restrict__ out, int N)
{
    extern __shared__ float sm[];
    const uint32_t sbase = smem_u32(sm);

    const int tid = threadIdx.x;
    const int wid = tid >> 5;
    const int lane = tid & 31;
    const int gid = lane >> 2;
    const int tig = lane & 3;
    const int wm = wid >> 1;
    const int wn = wid & 1;
    const int blk = blockIdx.x;

    const float* X;
    int row0, brow0, mode;   // mode: 0=q, 1=k, 2=v
    if (blk < 256)      { X = q_orig; row0 = blk * 128;         brow0 = 0; mode = 0; }
    else if (blk < 320) { X = k_orig; row0 = (blk - 256) * 128; brow0 = 0; mode = 1; }
    else {
        int vblk = blk - 320;
        X = v; row0 = (vblk >> 1) * 128; brow0 = 64 + (vblk & 1) * 64; mode = 2;
    }
    const bool qrows = (mode == 0);

    auto load_stage = [&](int s, int kc) {
        uint32_t abase = sbase + s * STAGE_BYTES;
        uint32_t bbase = abase + A_BYTES;
#pragma unroll
        for (int i = 0; i < 4; ++i) {
            int it = tid + 256 * i;
            int r = it >> 3, c4 = it & 7;
            const float* src;
            if (qrows) {
                int gr = row0 + r;
                src = X + (size_t)(gr >> 2) * 4096 + (size_t)(kc >> 2) * 512
                        + (size_t)(gr & 3) * 128 + (kc & 3) * 32 + c4 * 4;
            } else {
                src = X + (size_t)(row0 + r) * 1024 + kc * 32 + c4 * 4;
            }
            cp_async16(abase + (r * A_STRIDE + c4 * 4) * 4, src);
        }
#pragma unroll
        for (int i = 0; i < 2; ++i) {
            int it = tid + 256 * i;
            int r = it >> 3, c4 = it & 7;
            const float* src = B_all + (size_t)(brow0 + r) * 1024 + kc * 32 + c4 * 4;
            cp_async16(bbase + (r * A_STRIDE + c4 * 4) * 4, src);
        }
        CP_COMMIT();
    };

    float acc[2][4][4];
#pragma unroll
    for (int t = 0; t < 2; ++t)
#pragma unroll
        for (int n = 0; n < 4; ++n)
#pragma unroll
            for (int e = 0; e < 4; ++e) acc[t][n][e] = 0.f;

    load_stage(0, 0);

    for (int kc = 0; kc < 32; ++kc) {
        int s = kc & 1;
        if (kc + 1 < 32) {
            load_stage(s ^ 1, kc + 1);
            asm volatile("cp.async.wait_group 1;" ::: "memory");
        } else {
            asm volatile("cp.async.wait_group 0;" ::: "memory");
        }
        __syncthreads();

        const float* A_sh = sm + s * (STAGE_BYTES / 4);
        const float* B_sh = A_sh + (A_BYTES / 4);
#pragma unroll
        for (int k0 = 0; k0 < 32; k0 += 8) {
            uint32_t a[2][4];
#pragma unroll
            for (int t = 0; t < 2; ++t) {
                int ar = wm * 32 + t * 16;
                const float* p0 = A_sh + (ar + gid) * A_STRIDE + k0 + tig;
                const float* p1 = A_sh + (ar + gid + 8) * A_STRIDE + k0 + tig;
                a[t][0] = tf32_bits(p0[0]);
                a[t][1] = tf32_bits(p1[0]);
                a[t][2] = tf32_bits(p0[4]);
                a[t][3] = tf32_bits(p1[4]);
            }
            uint32_t b[4][2];
#pragma unroll
            for (int n = 0; n < 4; ++n) {
                int bc = wn * 32 + n * 8 + gid;
                const float* p = B_sh + bc * A_STRIDE + k0 + tig;
                b[n][0] = __float_as_uint(p[0]);
                b[n][1] = __float_as_uint(p[4]);
            }
#pragma unroll
            for (int t = 0; t < 2; ++t)
#pragma unroll
                for (int n = 0; n < 4; ++n)
                    MMA_TF32(acc[t][n], a[t], b[n]);
        }
        __syncthreads();
    }

    // epilogue
#pragma unroll
    for (int t = 0; t < 2; ++t) {
#pragma unroll
        for (int half = 0; half < 2; ++half) {
            int row = wm * 32 + t * 16 + gid + half * 8;
            int gr = row0 + row;
            float* op;
            if (mode == 0)
                op = out + (size_t)(gr >> 2) * 512 + (size_t)(gr & 3) * 128 + 64;
            else if (mode == 1)
                op = out + (size_t)N * 512 + (size_t)gr * 128 + 64;
            else
                op = w_scratch + (size_t)gr * 128 + (brow0 - 64);
#pragma unroll
            for (int n = 0; n < 4; ++n) {
                int col = wn * 32 + n * 8 + 2 * tig;
                float2 vv;
                vv.x = acc[t][n][half * 2 + 0];
                vv.y = acc[t][n][half * 2 + 1];
                *(float2*)(op + col) = vv;
            }
        }
    }
}

// ---------------------------------------------------------------------------
// Norm: weights[b,j] = sqrt(sum_{c<32} w_scratch[b][j*32+c]^2)
// ---------------------------------------------------------------------------
__global__ __launch_bounds__(256) void norm_kernel(float* __restrict__ out, int N)
{
    int t = blockIdx.x * blockDim.x + threadIdx.x;   // N*4 threads
    if (t >= N * 4) return;
    int b = t >> 2, j = t & 3;
    const float4* p = (const float4*)(w_scratch + (size_t)b * 128 + j * 32);
    float s = 0.f;
#pragma unroll
    for (int i = 0; i < 8; ++i) {
        float4 x = p[i];
        s += x.x * x.x + x.y * x.y + x.z * x.z + x.w * x.w;
    }
    out[(size_t)N * 512 + (size_t)N * 128 + t] = sqrtf(s);
}

// ---------------------------------------------------------------------------
extern "C" void kernel_launch(void* const* d_in, const int* in_sizes, int n_in,
                              void* d_out, int out_size)
{
    const float* q      = (const float*)d_in[0];
    const float* k      = (const float*)d_in[1];
    const float* v      = (const float*)d_in[2];
    const float* q_orig = (const float*)d_in[3];
    const float* k_orig = (const float*)d_in[4];
    const float* qk_w   = (const float*)d_in[5];
    const float* W      = (const float*)d_in[6];
    const float* vt     = (const float*)d_in[7];
    float* out = (float*)d_out;
    const int N = in_sizes[0] / (32 * 128);   // 8192

    cudaFuncSetAttribute(fused_gemm_kernel,
                         cudaFuncAttributeMaxDynamicSharedMemorySize, GEMM_SMEM);

    build_B_kernel<<<192, 1024>>>(qk_w, W, vt);
    rope_kernel<<<N, 256>>>(q, k, qk_w, out, N);
    fused_gemm_kernel<<<448, 256, GEMM_SMEM>>>(q_orig, k_orig, v, out, N);
    norm_kernel<<<(N * 4 + 255) / 256, 256>>>(out, N);
}

// round 8
// speedup vs baseline: 3.2397x; 1.0200x over previous
#include <cuda_runtime.h>
#include <stdint.h>
#include <math.h>

// ===========================================================================
// B_all[64][1024] : composed nope map (index cols 64..127). tf32-rounded.
// B_v[128][128]   : v-weights map, row = gg*16 + j*4 + r, col = d. tf32-rounded.
// ===========================================================================
__device__ float B_all[64 * 1024];
__device__ float B_v[128 * 128];

__device__ __forceinline__ float to_tf32(float x) {
    float r; asm("cvt.rna.tf32.f32 %0, %1;" : "=f"(r) : "f"(x)); return r;
}
__device__ __forceinline__ uint32_t tf32_bits(float x) {
    float r; asm("cvt.rna.tf32.f32 %0, %1;" : "=f"(r) : "f"(x));
    return __float_as_uint(r);
}
__device__ __forceinline__ uint32_t smem_u32(const void* p) {
    uint32_t a;
    asm("{ .reg .u64 t; cvta.to.shared.u64 t, %1; cvt.u32.u64 %0, t; }" : "=r"(a) : "l"(p));
    return a;
}
__device__ __forceinline__ void cp_async16(uint32_t dst, const void* src) {
    asm volatile("cp.async.cg.shared.global [%0], [%1], 16;"
                 :: "r"(dst), "l"(src) : "memory");
}
#define CP_COMMIT() asm volatile("cp.async.commit_group;" ::: "memory")
#define CP_WAIT2()  asm volatile("cp.async.wait_group 2;" ::: "memory")

#define MMA_TF32(c, a, b) \
    asm volatile( \
        "mma.sync.aligned.m16n8k8.row.col.f32.tf32.tf32.f32 " \
        "{%0,%1,%2,%3}, {%4,%5,%6,%7}, {%8,%9}, {%0,%1,%2,%3};" \
        : "+f"((c)[0]), "+f"((c)[1]), "+f"((c)[2]), "+f"((c)[3]) \
        : "r"((a)[0]), "r"((a)[1]), "r"((a)[2]), "r"((a)[3]), \
          "r"((b)[0]), "r"((b)[1]))

// ---------------------------------------------------------------------------
// Rope path (scalar, DRAM-bound) + B-matrix build folded into blocks 0..79.
// One block per token; 16-tap weighted gathers with weights qk_w[:, :, 0].
// ---------------------------------------------------------------------------
__global__ __launch_bounds__(256) void rope_build_kernel(
    const float* __restrict__ q,      // [N,32,128]
    const float* __restrict__ k,      // [N,8,128]
    const float* __restrict__ qk_w,   // [32,16,16]
    const float* __restrict__ W,      // [64,960]
    const float* __restrict__ vt,     // [32,128,4]
    float* __restrict__ out, int N)
{
    __shared__ float q_s[4096];
    __shared__ float k_s[1024];
    __shared__ float w0t[512];        // [c][n2]
    const int b = blockIdx.x;
    const int t = threadIdx.x;

    const float4* qg = (const float4*)(q + (size_t)b * 4096);
    float4* qs4 = (float4*)q_s;
#pragma unroll
    for (int i = 0; i < 4; ++i) qs4[t + 256 * i] = qg[t + 256 * i];
    ((float4*)k_s)[t] = ((const float4*)(k + (size_t)b * 1024))[t];
#pragma unroll
    for (int i = 0; i < 2; ++i) {
        int idx = t + 256 * i;
        int c = idx >> 5, n2 = idx & 31;
        w0t[idx] = qk_w[n2 * 256 + c * 16];
    }
    __syncthreads();

    {
        const int j = t >> 6, part = (t >> 5) & 1, n2 = t & 31;
        const int dbase = ((n2 & 15) << 2) + (n2 >> 4) + (part << 6);
        float acc = 0.f;
#pragma unroll
        for (int c = 0; c < 16; ++c) {
            int g = c & 7, p = c >> 3;
            acc += w0t[c * 32 + n2] * q_s[((g << 2) + j) * 128 + dbase + (p << 1)];
        }
        out[(size_t)b * 512 + j * 128 + part * 32 + n2] = acc;
    }
    if (t < 64) {
        const int part = t >> 5, n2 = t & 31;
        const int dbase = ((n2 & 15) << 2) + (n2 >> 4) + (part << 6);
        float acc = 0.f;
#pragma unroll
        for (int c = 0; c < 16; ++c) {
            int g = c & 7, p = c >> 3;
            acc += w0t[c * 32 + n2] * k_s[(g << 7) + dbase + (p << 1)];
        }
        out[(size_t)N * 512 + (size_t)b * 128 + part * 32 + n2] = acc;
    }

    // ---- build duty (blocks 0..79), hidden under the rope launch ----
    if (b < 64) {
#pragma unroll
        for (int i = 0; i < 4; ++i) {
            int kk = t + 256 * i;
            int g = kk >> 7, dfull = kk & 127;
            int part = dfull >> 6, d = dfull & 63;
            int f = d & 1, p = (d >> 1) & 1, m = d >> 2;
            int n2 = f * 16 + m;
            const float* wrow = W + b * 960 + part * 480 + n2 * 15;
            const float* qrow = qk_w + n2 * 256 + (p * 8 + g) * 16;
            float acc = 0.f;
#pragma unroll
            for (int r = 1; r < 16; ++r)
                acc += wrow[r - 1] * qrow[r];
            B_all[b * 1024 + kk] = to_tf32(acc);
        }
    } else if (b < 80) {
#pragma unroll
        for (int i = 0; i < 4; ++i) {
            int e = (b - 64) * 1024 + t + 256 * i;    // 0..16383
            int row = e >> 7, d = e & 127;            // row = gg*16 + j*4 + r
            int gg = row >> 4, j = (row >> 2) & 3, r = row & 3;
            B_v[e] = to_tf32(vt[(size_t)(gg * 4 + j) * 512 + d * 4 + r]);
        }
    }
}

// ---------------------------------------------------------------------------
// Fused GEMM (tf32 mma.sync), 4-stage cp.async pipeline. 384 blocks:
//  blk [0,256)   : A = q_orig (rows (b,j)), B_all, out cols 64..127
//  blk [256,320) : A = k_orig (rows b),     B_all, out cols 64..127
//  blk [320,384) : A = v (128 tokens), block-diagonal B_v (K=128 per gg),
//                  norm computed in epilogue -> weights
// ---------------------------------------------------------------------------
static constexpr int A_STRIDE = 36;                    // floats
static constexpr int A_BYTES = 128 * A_STRIDE * 4;     // 18432
static constexpr int STAGE_BYTES = A_BYTES + 64 * A_STRIDE * 4;  // 27648
static constexpr int GEMM_SMEM = 4 * STAGE_BYTES;      // 110592

__global__ __launch_bounds__(256) void gemm_kernel(
    const float* __restrict__ q_orig, const float* __restrict__ k_orig,
    const float* __restrict__ v,
    float* __restrict__ out, int N)
{
    extern __shared__ float sm[];
    const uint32_t sbase = smem_u32(sm);

    const int tid = threadIdx.x;
    const int wid = tid >> 5;
    const int lane = tid & 31;
    const int gid = lane >> 2;
    const int tig = lane & 3;
    const int wm = wid >> 1;
    const int wn = wid & 1;
    const int blk = blockIdx.x;

    if (blk < 320) {
        // ================= q/k nope path =================
        const float* X;
        int row0, mode;
        if (blk < 256) { X = q_orig; row0 = blk * 128;         mode = 0; }
        else           { X = k_orig; row0 = (blk - 256) * 128; mode = 1; }
        const bool qrows = (mode == 0);

        auto load_stage = [&](int s, int kc) {
            uint32_t abase = sbase + s * STAGE_BYTES;
            uint32_t bbase = abase + A_BYTES;
#pragma unroll
            for (int i = 0; i < 4; ++i) {
                int it = tid + 256 * i;
                int r = it >> 3, c4 = it & 7;
                const float* src;
                if (qrows) {
                    int gr = row0 + r;
                    src = X + (size_t)(gr >> 2) * 4096 + (size_t)(kc >> 2) * 512
                            + (size_t)(gr & 3) * 128 + (kc & 3) * 32 + c4 * 4;
                } else {
                    src = X + (size_t)(row0 + r) * 1024 + kc * 32 + c4 * 4;
                }
                cp_async16(abase + (r * A_STRIDE + c4 * 4) * 4, src);
            }
#pragma unroll
            for (int i = 0; i < 2; ++i) {
                int it = tid + 256 * i;
                int r = it >> 3, c4 = it & 7;
                cp_async16(bbase + (r * A_STRIDE + c4 * 4) * 4,
                           B_all + (size_t)r * 1024 + kc * 32 + c4 * 4);
            }
            CP_COMMIT();
        };

        float acc[2][4][4];
#pragma unroll
        for (int t = 0; t < 2; ++t)
#pragma unroll
            for (int n = 0; n < 4; ++n)
#pragma unroll
                for (int e = 0; e < 4; ++e) acc[t][n][e] = 0.f;

        load_stage(0, 0); load_stage(1, 1); load_stage(2, 2);

        for (int kc = 0; kc < 32; ++kc) {
            CP_WAIT2();
            __syncthreads();
            if (kc + 3 < 32) load_stage((kc + 3) & 3, kc + 3);
            else CP_COMMIT();

            const float* A_sh = sm + (kc & 3) * (STAGE_BYTES / 4);
            const float* B_sh = A_sh + (A_BYTES / 4);
#pragma unroll
            for (int k0 = 0; k0 < 32; k0 += 8) {
                uint32_t a[2][4];
#pragma unroll
                for (int t = 0; t < 2; ++t) {
                    int ar = wm * 32 + t * 16;
                    const float* p0 = A_sh + (ar + gid) * A_STRIDE + k0 + tig;
                    const float* p1 = A_sh + (ar + gid + 8) * A_STRIDE + k0 + tig;
                    a[t][0] = tf32_bits(p0[0]);
                    a[t][1] = tf32_bits(p1[0]);
                    a[t][2] = tf32_bits(p0[4]);
                    a[t][3] = tf32_bits(p1[4]);
                }
                uint32_t b[4][2];
#pragma unroll
                for (int n = 0; n < 4; ++n) {
                    const float* p = B_sh + (wn * 32 + n * 8 + gid) * A_STRIDE + k0 + tig;
                    b[n][0] = __float_as_uint(p[0]);
                    b[n][1] = __float_as_uint(p[4]);
                }
#pragma unroll
                for (int t = 0; t < 2; ++t)
#pragma unroll
                    for (int n = 0; n < 4; ++n)
                        MMA_TF32(acc[t][n], a[t], b[n]);
            }
        }

#pragma unroll
        for (int t = 0; t < 2; ++t) {
#pragma unroll
            for (int half = 0; half < 2; ++half) {
                int row = wm * 32 + t * 16 + gid + half * 8;
                int gr = row0 + row;
                float* op = (mode == 0)
                    ? out + (size_t)(gr >> 2) * 512 + (size_t)(gr & 3) * 128 + 64
                    : out + (size_t)N * 512 + (size_t)gr * 128 + 64;
#pragma unroll
                for (int n = 0; n < 4; ++n) {
                    int col = wn * 32 + n * 8 + 2 * tig;
                    float2 vv;
                    vv.x = acc[t][n][half * 2 + 0];
                    vv.y = acc[t][n][half * 2 + 1];
                    *(float2*)(op + col) = vv;
                }
            }
        }
    } else {
        // ================= v-weights + norm path =================
        const int b0 = (blk - 320) * 128;

        auto load_stage_v = [&](int s, int kc) {
            int gg = kc >> 2, sub = kc & 3;
            uint32_t abase = sbase + s * STAGE_BYTES;
            uint32_t bbase = abase + A_BYTES;
#pragma unroll
            for (int i = 0; i < 4; ++i) {
                int it = tid + 256 * i;
                int r = it >> 3, c4 = it & 7;
                cp_async16(abase + (r * A_STRIDE + c4 * 4) * 4,
                           v + (size_t)(b0 + r) * 1024 + gg * 128 + sub * 32 + c4 * 4);
            }
            if (tid < 128) {
                int r = tid >> 3, c4 = tid & 7;
                cp_async16(bbase + (r * A_STRIDE + c4 * 4) * 4,
                           B_v + (size_t)(gg * 16 + r) * 128 + sub * 32 + c4 * 4);
            }
            CP_COMMIT();
        };

        float acc[2][4];
        float sq[2][2];
#pragma unroll
        for (int t = 0; t < 2; ++t) {
#pragma unroll
            for (int e = 0; e < 4; ++e) acc[t][e] = 0.f;
            sq[t][0] = sq[t][1] = 0.f;
        }

        load_stage_v(0, 0); load_stage_v(1, 1); load_stage_v(2, 2);

        for (int kc = 0; kc < 32; ++kc) {
            CP_WAIT2();
            __syncthreads();
            if (kc + 3 < 32) load_stage_v((kc + 3) & 3, kc + 3);
            else CP_COMMIT();

            const float* A_sh = sm + (kc & 3) * (STAGE_BYTES / 4);
            const float* B_sh = A_sh + (A_BYTES / 4);
#pragma unroll
            for (int k0 = 0; k0 < 32; k0 += 8) {
                uint32_t a[2][4];
#pragma unroll
                for (int t = 0; t < 2; ++t) {
                    int ar = wm * 32 + t * 16;
                    const float* p0 = A_sh + (ar + gid) * A_STRIDE + k0 + tig;
                    const float* p1 = A_sh + (ar + gid + 8) * A_STRIDE + k0 + tig;
                    a[t][0] = tf32_bits(p0[0]);
                    a[t][1] = tf32_bits(p1[0]);
                    a[t][2] = tf32_bits(p0[4]);
                    a[t][3] = tf32_bits(p1[4]);
                }
                uint32_t b[2];
                {
                    const float* p = B_sh + (wn * 8 + gid) * A_STRIDE + k0 + tig;
                    b[0] = __float_as_uint(p[0]);
                    b[1] = __float_as_uint(p[4]);
                }
#pragma unroll
                for (int t = 0; t < 2; ++t)
                    MMA_TF32(acc[t], a[t], b);
            }
            if ((kc & 3) == 3) {   // end of this gg: fold squares, reset
#pragma unroll
                for (int t = 0; t < 2; ++t) {
                    sq[t][0] += acc[t][0] * acc[t][0] + acc[t][1] * acc[t][1];
                    sq[t][1] += acc[t][2] * acc[t][2] + acc[t][3] * acc[t][3];
#pragma unroll
                    for (int e = 0; e < 4; ++e) acc[t][e] = 0.f;
                }
            }
        }

        // norm epilogue: pair-fold over tig (both cols of partner share j)
        const int j = wn * 2 + (tig >> 1);
#pragma unroll
        for (int t = 0; t < 2; ++t) {
#pragma unroll
            for (int half = 0; half < 2; ++half) {
                float s = sq[t][half];
                s += __shfl_xor_sync(0xffffffffu, s, 1);
                if ((tig & 1) == 0) {
                    int row = wm * 32 + t * 16 + gid + half * 8;
                    out[(size_t)N * 640 + (size_t)(b0 + row) * 4 + j] = sqrtf(s);
                }
            }
        }
    }
}

// ---------------------------------------------------------------------------
extern "C" void kernel_launch(void* const* d_in, const int* in_sizes, int n_in,
                              void* d_out, int out_size)
{
    const float* q      = (const float*)d_in[0];
    const float* k      = (const float*)d_in[1];
    const float* v      = (const float*)d_in[2];
    const float* q_orig = (const float*)d_in[3];
    const float* k_orig = (const float*)d_in[4];
    const float* qk_w   = (const float*)d_in[5];
    const float* W      = (const float*)d_in[6];
    const float* vt     = (const float*)d_in[7];
    float* out = (float*)d_out;
    const int N = in_sizes[0] / (32 * 128);   // 8192

    cudaFuncSetAttribute(gemm_kernel,
                         cudaFuncAttributeMaxDynamicSharedMemorySize, GEMM_SMEM);

    rope_build_kernel<<<N, 256>>>(q, k, qk_w, W, vt, out, N);
    gemm_kernel<<<384, 256, GEMM_SMEM>>>(q_orig, k_orig, v, out, N);
}

// round 10
// speedup vs baseline: 3.3152x; 1.0233x over previous
#include <cuda_runtime.h>
#include <stdint.h>
#include <math.h>

// ===========================================================================
// B_all[64][1024] : composed nope map (index cols 64..127). tf32-rounded.
// B_v[128][128]   : v-weights map, row = gg*16 + j*4 + r, col = d. tf32-rounded.
// ===========================================================================
__device__ float B_all[64 * 1024];
__device__ float B_v[128 * 128];

__device__ __forceinline__ float to_tf32(float x) {
    float r; asm("cvt.rna.tf32.f32 %0, %1;" : "=f"(r) : "f"(x)); return r;
}
__device__ __forceinline__ uint32_t tf32_bits(float x) {
    float r; asm("cvt.rna.tf32.f32 %0, %1;" : "=f"(r) : "f"(x));
    return __float_as_uint(r);
}
__device__ __forceinline__ uint32_t smem_u32(const void* p) {
    uint32_t a;
    asm("{ .reg .u64 t; cvta.to.shared.u64 t, %1; cvt.u32.u64 %0, t; }" : "=r"(a) : "l"(p));
    return a;
}
__device__ __forceinline__ void cp_async16(uint32_t dst, const void* src) {
    asm volatile("cp.async.cg.shared.global [%0], [%1], 16;"
                 :: "r"(dst), "l"(src) : "memory");
}
#define CP_COMMIT() asm volatile("cp.async.commit_group;" ::: "memory")

#define MMA_TF32(c, a, b) \
    asm volatile( \
        "mma.sync.aligned.m16n8k8.row.col.f32.tf32.tf32.f32 " \
        "{%0,%1,%2,%3}, {%4,%5,%6,%7}, {%8,%9}, {%0,%1,%2,%3};" \
        : "+f"((c)[0]), "+f"((c)[1]), "+f"((c)[2]), "+f"((c)[3]) \
        : "r"((a)[0]), "r"((a)[1]), "r"((a)[2]), "r"((a)[3]), \
          "r"((b)[0]), "r"((b)[1]))

// ---------------------------------------------------------------------------
// Build B_all + B_v: 320 blocks x 256 threads, one element per thread.
// ---------------------------------------------------------------------------
__global__ __launch_bounds__(256) void build_B_kernel(
    const float* __restrict__ qk_w,   // [32][16][16]
    const float* __restrict__ W,      // [64][960]
    const float* __restrict__ vt)     // [32][128][4]
{
    int e = blockIdx.x * 256 + threadIdx.x;   // 81920 total
    if (e < 65536) {
        int o = e >> 10, kk = e & 1023;
        int g = kk >> 7, dfull = kk & 127;
        int part = dfull >> 6, d = dfull & 63;
        int f = d & 1, p = (d >> 1) & 1, m = d >> 2;
        int n2 = f * 16 + m;
        const float* wrow = W + o * 960 + part * 480 + n2 * 15;
        const float* qrow = qk_w + n2 * 256 + (p * 8 + g) * 16;
        float acc = 0.f;
#pragma unroll
        for (int r = 1; r < 16; ++r)
            acc += __ldg(wrow + r - 1) * __ldg(qrow + r);
        B_all[e] = to_tf32(acc);
    } else {
        int e2 = e - 65536;                   // 0..16383
        int row = e2 >> 7, d = e2 & 127;      // row = gg*16 + j*4 + r
        int gg = row >> 4, j = (row >> 2) & 3, r = row & 3;
        B_v[e2] = to_tf32(__ldg(vt + (size_t)(gg * 4 + j) * 512 + d * 4 + r));
    }
}

// ---------------------------------------------------------------------------
// Rope path (scalar, DRAM-bound): per token, 256 q outputs + 64 k outputs,
// each a 16-tap weighted gather with weights qk_w[:, :, 0]. One block/token.
// ---------------------------------------------------------------------------
__global__ __launch_bounds__(256) void rope_kernel(
    const float* __restrict__ q,      // [N,32,128]
    const float* __restrict__ k,      // [N,8,128]
    const float* __restrict__ qk_w,   // [32,16,16]
    float* __restrict__ out, int N)
{
    __shared__ float q_s[4096];
    __shared__ float k_s[1024];
    __shared__ float w0t[512];        // [c][n2]
    const int b = blockIdx.x;
    const int t = threadIdx.x;

    const float4* qg = (const float4*)(q + (size_t)b * 4096);
    float4* qs4 = (float4*)q_s;
#pragma unroll
    for (int i = 0; i < 4; ++i) qs4[t + 256 * i] = qg[t + 256 * i];
    ((float4*)k_s)[t] = ((const float4*)(k + (size_t)b * 1024))[t];
#pragma unroll
    for (int i = 0; i < 2; ++i) {
        int idx = t + 256 * i;
        int c = idx >> 5, n2 = idx & 31;
        w0t[idx] = qk_w[n2 * 256 + c * 16];
    }
    __syncthreads();

    {
        const int j = t >> 6, part = (t >> 5) & 1, n2 = t & 31;
        const int dbase = ((n2 & 15) << 2) + (n2 >> 4) + (part << 6);
        float acc = 0.f;
#pragma unroll
        for (int c = 0; c < 16; ++c) {
            int g = c & 7, p = c >> 3;
            acc += w0t[c * 32 + n2] * q_s[((g << 2) + j) * 128 + dbase + (p << 1)];
        }
        out[(size_t)b * 512 + j * 128 + part * 32 + n2] = acc;
    }
    if (t < 64) {
        const int part = t >> 5, n2 = t & 31;
        const int dbase = ((n2 & 15) << 2) + (n2 >> 4) + (part << 6);
        float acc = 0.f;
#pragma unroll
        for (int c = 0; c < 16; ++c) {
            int g = c & 7, p = c >> 3;
            acc += w0t[c * 32 + n2] * k_s[(g << 7) + dbase + (p << 1)];
        }
        out[(size_t)N * 512 + (size_t)b * 128 + part * 32 + n2] = acc;
    }
}

// ---------------------------------------------------------------------------
// Fused GEMM (tf32 mma.sync), 2-stage cp.async pipeline, 3 blocks/SM. 384 blks:
//  blk [0,256)   : A = q_orig (rows (b,j)), B_all, out cols 64..127
//  blk [256,320) : A = k_orig (rows b),     B_all, out cols 64..127
//  blk [320,384) : A = v (128 tokens), block-diagonal B_v (K=128 per gg),
//                  norm computed in epilogue -> weights
// ---------------------------------------------------------------------------
static constexpr int A_STRIDE = 36;                    // floats
static constexpr int A_BYTES = 128 * A_STRIDE * 4;     // 18432
static constexpr int STAGE_BYTES = A_BYTES + 64 * A_STRIDE * 4;  // 27648
static constexpr int GEMM_SMEM = 2 * STAGE_BYTES;      // 55296

__global__ __launch_bounds__(256, 3) void gemm_kernel(
    const float* __restrict__ q_orig, const float* __restrict__ k_orig,
    const float* __restrict__ v,
    float* __restrict__ out, int N)
{
    extern __shared__ float sm[];
    const uint32_t sbase = smem_u32(sm);

    const int tid = threadIdx.x;
    const int wid = tid >> 5;
    const int lane = tid & 31;
    const int gid = lane >> 2;
    const int tig = lane & 3;
    const int wm = wid >> 1;
    const int wn = wid & 1;
    const int blk = blockIdx.x;

    if (blk < 320) {
        // ================= q/k nope path =================
        const float* X;
        int row0, mode;
        if (blk < 256) { X = q_orig; row0 = blk * 128;         mode = 0; }
        else           { X = k_orig; row0 = (blk - 256) * 128; mode = 1; }
        const bool qrows = (mode == 0);

        auto load_stage = [&](int s, int kc) {
            uint32_t abase = sbase + s * STAGE_BYTES;
            uint32_t bbase = abase + A_BYTES;
#pragma unroll
            for (int i = 0; i < 4; ++i) {
                int it = tid + 256 * i;
                int r = it >> 3, c4 = it & 7;
                const float* src;
                if (qrows) {
                    int gr = row0 + r;
                    src = X + (size_t)(gr >> 2) * 4096 + (size_t)(kc >> 2) * 512
                            + (size_t)(gr & 3) * 128 + (kc & 3) * 32 + c4 * 4;
                } else {
                    src = X + (size_t)(row0 + r) * 1024 + kc * 32 + c4 * 4;
                }
                cp_async16(abase + (r * A_STRIDE + c4 * 4) * 4, src);
            }
#pragma unroll
            for (int i = 0; i < 2; ++i) {
                int it = tid + 256 * i;
                int r = it >> 3, c4 = it & 7;
                cp_async16(bbase + (r * A_STRIDE + c4 * 4) * 4,
                           B_all + (size_t)r * 1024 + kc * 32 + c4 * 4);
            }
            CP_COMMIT();
        };

        float acc[2][4][4];
#pragma unroll
        for (int t = 0; t < 2; ++t)
#pragma unroll
            for (int n = 0; n < 4; ++n)
#pragma unroll
                for (int e = 0; e < 4; ++e) acc[t][n][e] = 0.f;

        load_stage(0, 0);

        for (int kc = 0; kc < 32; ++kc) {
            int s = kc & 1;
            if (kc + 1 < 32) {
                load_stage(s ^ 1, kc + 1);
                asm volatile("cp.async.wait_group 1;" ::: "memory");
            } else {
                asm volatile("cp.async.wait_group 0;" ::: "memory");
            }
            __syncthreads();

            const float* A_sh = sm + s * (STAGE_BYTES / 4);
            const float* B_sh = A_sh + (A_BYTES / 4);
#pragma unroll
            for (int k0 = 0; k0 < 32; k0 += 8) {
                uint32_t a[2][4];
#pragma unroll
                for (int t = 0; t < 2; ++t) {
                    int ar = wm * 32 + t * 16;
                    const float* p0 = A_sh + (ar + gid) * A_STRIDE + k0 + tig;
                    const float* p1 = A_sh + (ar + gid + 8) * A_STRIDE + k0 + tig;
                    a[t][0] = tf32_bits(p0[0]);
                    a[t][1] = tf32_bits(p1[0]);
                    a[t][2] = tf32_bits(p0[4]);
                    a[t][3] = tf32_bits(p1[4]);
                }
                uint32_t b[4][2];
#pragma unroll
                for (int n = 0; n < 4; ++n) {
                    const float* p = B_sh + (wn * 32 + n * 8 + gid) * A_STRIDE + k0 + tig;
                    b[n][0] = __float_as_uint(p[0]);
                    b[n][1] = __float_as_uint(p[4]);
                }
#pragma unroll
                for (int t = 0; t < 2; ++t)
#pragma unroll
                    for (int n = 0; n < 4; ++n)
                        MMA_TF32(acc[t][n], a[t], b[n]);
            }
            __syncthreads();
        }

#pragma unroll
        for (int t = 0; t < 2; ++t) {
#pragma unroll
            for (int half = 0; half < 2; ++half) {
                int row = wm * 32 + t * 16 + gid + half * 8;
                int gr = row0 + row;
                float* op = (mode == 0)
                    ? out + (size_t)(gr >> 2) * 512 + (size_t)(gr & 3) * 128 + 64
                    : out + (size_t)N * 512 + (size_t)gr * 128 + 64;
#pragma unroll
                for (int n = 0; n < 4; ++n) {
                    int col = wn * 32 + n * 8 + 2 * tig;
                    float2 vv;
                    vv.x = acc[t][n][half * 2 + 0];
                    vv.y = acc[t][n][half * 2 + 1];
                    *(float2*)(op + col) = vv;
                }
            }
        }
    } else {
        // ================= v-weights + norm path =================
        const int b0 = (blk - 320) * 128;

        auto load_stage_v = [&](int s, int kc) {
            int gg = kc >> 2, sub = kc & 3;
            uint32_t abase = sbase + s * STAGE_BYTES;
            uint32_t bbase = abase + A_BYTES;
#pragma unroll
            for (int i = 0; i < 4; ++i) {
                int it = tid + 256 * i;
                int r = it >> 3, c4 = it & 7;
                cp_async16(abase + (r * A_STRIDE + c4 * 4) * 4,
                           v + (size_t)(b0 + r) * 1024 + gg * 128 + sub * 32 + c4 * 4);
            }
            if (tid < 128) {
                int r = tid >> 3, c4 = tid & 7;
                cp_async16(bbase + (r * A_STRIDE + c4 * 4) * 4,
                           B_v + (size_t)(gg * 16 + r) * 128 + sub * 32 + c4 * 4);
            }
            CP_COMMIT();
        };

        float acc[2][4];
        float sq[2][2];
#pragma unroll
        for (int t = 0; t < 2; ++t) {
#pragma unroll
            for (int e = 0; e < 4; ++e) acc[t][e] = 0.f;
            sq[t][0] = sq[t][1] = 0.f;
        }

        load_stage_v(0, 0);

        for (int kc = 0; kc < 32; ++kc) {
            int s = kc & 1;
            if (kc + 1 < 32) {
                load_stage_v(s ^ 1, kc + 1);
                asm volatile("cp.async.wait_group 1;" ::: "memory");
            } else {
                asm volatile("cp.async.wait_group 0;" ::: "memory");
            }
            __syncthreads();

            const float* A_sh = sm + s * (STAGE_BYTES / 4);
            const float* B_sh = A_sh + (A_BYTES / 4);
#pragma unroll
            for (int k0 = 0; k0 < 32; k0 += 8) {
                uint32_t a[2][4];
#pragma unroll
                for (int t = 0; t < 2; ++t) {
                    int ar = wm * 32 + t * 16;
                    const float* p0 = A_sh + (ar + gid) * A_STRIDE + k0 + tig;
                    const float* p1 = A_sh + (ar + gid + 8) * A_STRIDE + k0 + tig;
                    a[t][0] = tf32_bits(p0[0]);
                    a[t][1] = tf32_bits(p1[0]);
                    a[t][2] = tf32_bits(p0[4]);
                    a[t][3] = tf32_bits(p1[4]);
                }
                uint32_t b[2];
                {
                    const float* p = B_sh + (wn * 8 + gid) * A_STRIDE + k0 + tig;
                    b[0] = __float_as_uint(p[0]);
                    b[1] = __float_as_uint(p[4]);
                }
#pragma unroll
                for (int t = 0; t < 2; ++t)
                    MMA_TF32(acc[t], a[t], b);
            }
            __syncthreads();
            if ((kc & 3) == 3) {   // end of this gg: fold squares, reset
#pragma unroll
                for (int t = 0; t < 2; ++t) {
                    sq[t][0] += acc[t][0] * acc[t][0] + acc[t][1] * acc[t][1];
                    sq[t][1] += acc[t][2] * acc[t][2] + acc[t][3] * acc[t][3];
#pragma unroll
                    for (int e = 0; e < 4; ++e) acc[t][e] = 0.f;
                }
            }
        }

        // norm epilogue: pair-fold over tig (both cols of partner share j)
        const int j = wn * 2 + (tig >> 1);
#pragma unroll
        for (int t = 0; t < 2; ++t) {
#pragma unroll
            for (int half = 0; half < 2; ++half) {
                float s = sq[t][half];
                s += __shfl_xor_sync(0xffffffffu, s, 1);
                if ((tig & 1) == 0) {
                    int row = wm * 32 + t * 16 + gid + half * 8;
                    out[(size_t)N * 640 + (size_t)(b0 + row) * 4 + j] = sqrtf(s);
                }
            }
        }
    }
}

// ---------------------------------------------------------------------------
extern "C" void kernel_launch(void* const* d_in, const int* in_sizes, int n_in,
                              void* d_out, int out_size)
{
    const float* q      = (const float*)d_in[0];
    const float* k      = (const float*)d_in[1];
    const float* v      = (const float*)d_in[2];
    const float* q_orig = (const float*)d_in[3];
    const float* k_orig = (const float*)d_in[4];
    const float* qk_w   = (const float*)d_in[5];
    const float* W      = (const float*)d_in[6];
    const float* vt     = (const float*)d_in[7];
    float* out = (float*)d_out;
    const int N = in_sizes[0] / (32 * 128);   // 8192

    cudaFuncSetAttribute(gemm_kernel,
                         cudaFuncAttributeMaxDynamicSharedMemorySize, GEMM_SMEM);

    // persistent side stream + events for fork/join inside graph capture
    static cudaStream_t s1 = nullptr;
    static cudaEvent_t e_fork = nullptr, e_join = nullptr;
    if (!s1) {
        cudaStreamCreateWithFlags(&s1, cudaStreamNonBlocking);
        cudaEventCreateWithFlags(&e_fork, cudaEventDisableTiming);
        cudaEventCreateWithFlags(&e_join, cudaEventDisableTiming);
    }

    bool forked = (s1 != nullptr) &&
                  (cudaEventRecord(e_fork, 0) == cudaSuccess) &&
                  (cudaStreamWaitEvent(s1, e_fork, 0) == cudaSuccess);

    if (forked) {
        // rope (DRAM-heavy) on side stream, build+gemm on main stream — overlap
        rope_kernel<<<N, 256, 0, s1>>>(q, k, qk_w, out, N);
        build_B_kernel<<<320, 256>>>(qk_w, W, vt);
        gemm_kernel<<<384, 256, GEMM_SMEM>>>(q_orig, k_orig, v, out, N);
        cudaEventRecord(e_join, s1);
        cudaStreamWaitEvent(0, e_join, 0);
    } else {
        build_B_kernel<<<320, 256>>>(qk_w, W, vt);
        rope_kernel<<<N, 256>>>(q, k, qk_w, out, N);
        gemm_kernel<<<384, 256, GEMM_SMEM>>>(q_orig, k_orig, v, out, N);
    }
}

// round 11
// speedup vs baseline: 3.5385x; 1.0674x over previous
#include <cuda_runtime.h>
#include <stdint.h>
#include <math.h>

// ===========================================================================
// B_all[64][1024] : composed nope map (index cols 64..127). tf32-rounded.
// B_v[128][128]   : v-weights map, row = gg*16 + j*4 + r, col = d. tf32-rounded.
// ===========================================================================
__device__ float B_all[64 * 1024];
__device__ float B_v[128 * 128];

__device__ __forceinline__ float to_tf32(float x) {
    float r; asm("cvt.rna.tf32.f32 %0, %1;" : "=f"(r) : "f"(x)); return r;
}
__device__ __forceinline__ uint32_t tf32_bits(float x) {
    float r; asm("cvt.rna.tf32.f32 %0, %1;" : "=f"(r) : "f"(x));
    return __float_as_uint(r);
}
__device__ __forceinline__ uint32_t smem_u32(const void* p) {
    uint32_t a;
    asm("{ .reg .u64 t; cvta.to.shared.u64 t, %1; cvt.u32.u64 %0, t; }" : "=r"(a) : "l"(p));
    return a;
}
__device__ __forceinline__ void cp_async16(uint32_t dst, const void* src) {
    asm volatile("cp.async.cg.shared.global [%0], [%1], 16;"
                 :: "r"(dst), "l"(src) : "memory");
}
#define CP_COMMIT() asm volatile("cp.async.commit_group;" ::: "memory")

#define MMA_TF32(c, a, b) \
    asm volatile( \
        "mma.sync.aligned.m16n8k8.row.col.f32.tf32.tf32.f32 " \
        "{%0,%1,%2,%3}, {%4,%5,%6,%7}, {%8,%9}, {%0,%1,%2,%3};" \
        : "+f"((c)[0]), "+f"((c)[1]), "+f"((c)[2]), "+f"((c)[3]) \
        : "r"((a)[0]), "r"((a)[1]), "r"((a)[2]), "r"((a)[3]), \
          "r"((b)[0]), "r"((b)[1]))

// ---------------------------------------------------------------------------
// Build B_all + B_v: 320 blocks x 256 threads, one element per thread.
// ---------------------------------------------------------------------------
__global__ __launch_bounds__(256) void build_B_kernel(
    const float* __restrict__ qk_w,   // [32][16][16]
    const float* __restrict__ W,      // [64][960]
    const float* __restrict__ vt)     // [32][128][4]
{
    int e = blockIdx.x * 256 + threadIdx.x;   // 81920 total
    if (e < 65536) {
        int o = e >> 10, kk = e & 1023;
        int g = kk >> 7, dfull = kk & 127;
        int part = dfull >> 6, d = dfull & 63;
        int f = d & 1, p = (d >> 1) & 1, m = d >> 2;
        int n2 = f * 16 + m;
        const float* wrow = W + o * 960 + part * 480 + n2 * 15;
        const float* qrow = qk_w + n2 * 256 + (p * 8 + g) * 16;
        float acc = 0.f;
#pragma unroll
        for (int r = 1; r < 16; ++r)
            acc += __ldg(wrow + r - 1) * __ldg(qrow + r);
        B_all[e] = to_tf32(acc);
    } else {
        int e2 = e - 65536;                   // 0..16383
        int row = e2 >> 7, d = e2 & 127;      // row = gg*16 + j*4 + r
        int gg = row >> 4, j = (row >> 2) & 3, r = row & 3;
        B_v[e2] = to_tf32(__ldg(vt + (size_t)(gg * 4 + j) * 512 + d * 4 + r));
    }
}

// ---------------------------------------------------------------------------
// Rope path, register-only: each thread owns outputs (j,part,n2=m) and
// (j,part,n2=16+m); its 16+16 taps are the .x/.y/.z/.w of 8 float4 loads
// at row (g*4+j), cols part*64+4m..+3  (per-warp: contiguous 512B per g).
// 160 threads/token: t<128 -> q outputs, t>=128 -> k outputs.
// ---------------------------------------------------------------------------
__global__ __launch_bounds__(160) void rope_kernel(
    const float* __restrict__ q,      // [N,32,128]
    const float* __restrict__ k,      // [N,8,128]
    const float* __restrict__ qk_w,   // [32,16,16]
    float* __restrict__ out, int N)
{
    __shared__ float w0[512];         // [n2][c] : qk_w[n2][c][0]
    const int b = blockIdx.x;
    const int t = threadIdx.x;

    for (int i = t; i < 512; i += 160)
        w0[i] = __ldg(qk_w + (i >> 4) * 256 + (i & 15) * 16);
    __syncthreads();

    if (t < 128) {
        const int j = t >> 5, part = (t >> 4) & 1, m = t & 15;
        const float* wA = w0 + m * 16;
        const float* wB = w0 + (16 + m) * 16;
        const float* base = q + (size_t)b * 4096 + j * 128 + part * 64 + m * 4;
        float acc0 = 0.f, acc1 = 0.f;
#pragma unroll
        for (int g = 0; g < 8; ++g) {
            float4 f = *(const float4*)(base + g * 512);
            acc0 += wA[g] * f.x + wA[8 + g] * f.z;
            acc1 += wB[g] * f.y + wB[8 + g] * f.w;
        }
        float* op = out + (size_t)b * 512 + j * 128 + part * 32 + m;
        op[0]  = acc0;
        op[16] = acc1;
    } else {
        const int tt = t - 128;
        const int part = tt >> 4, m = tt & 15;
        const float* wA = w0 + m * 16;
        const float* wB = w0 + (16 + m) * 16;
        const float* base = k + (size_t)b * 1024 + part * 64 + m * 4;
        float acc0 = 0.f, acc1 = 0.f;
#pragma unroll
        for (int g = 0; g < 8; ++g) {
            float4 f = *(const float4*)(base + g * 128);
            acc0 += wA[g] * f.x + wA[8 + g] * f.z;
            acc1 += wB[g] * f.y + wB[8 + g] * f.w;
        }
        float* op = out + (size_t)N * 512 + (size_t)b * 128 + part * 32 + m;
        op[0]  = acc0;
        op[16] = acc1;
    }
}

// ---------------------------------------------------------------------------
// Fused GEMM (tf32 mma.sync), 2-stage cp.async pipeline, 3 blocks/SM. 384 blks:
//  blk [0,256)   : A = q_orig (rows (b,j)), B_all, out cols 64..127
//  blk [256,320) : A = k_orig (rows b),     B_all, out cols 64..127
//  blk [320,384) : A = v (128 tokens), block-diagonal B_v (K=128 per gg),
//                  norm computed in epilogue -> weights
// ---------------------------------------------------------------------------
static constexpr int A_STRIDE = 36;                    // floats
static constexpr int A_BYTES = 128 * A_STRIDE * 4;     // 18432
static constexpr int STAGE_BYTES = A_BYTES + 64 * A_STRIDE * 4;  // 27648
static constexpr int GEMM_SMEM = 2 * STAGE_BYTES;      // 55296

__global__ __launch_bounds__(256, 3) void gemm_kernel(
    const float* __restrict__ q_orig, const float* __restrict__ k_orig,
    const float* __restrict__ v,
    float* __restrict__ out, int N)
{
    extern __shared__ float sm[];
    const uint32_t sbase = smem_u32(sm);

    const int tid = threadIdx.x;
    const int wid = tid >> 5;
    const int lane = tid & 31;
    const int gid = lane >> 2;
    const int tig = lane & 3;
    const int wm = wid >> 1;
    const int wn = wid & 1;
    const int blk = blockIdx.x;

    if (blk < 320) {
        // ================= q/k nope path =================
        const float* X;
        int row0, mode;
        if (blk < 256) { X = q_orig; row0 = blk * 128;         mode = 0; }
        else           { X = k_orig; row0 = (blk - 256) * 128; mode = 1; }
        const bool qrows = (mode == 0);

        auto load_stage = [&](int s, int kc) {
            uint32_t abase = sbase + s * STAGE_BYTES;
            uint32_t bbase = abase + A_BYTES;
#pragma unroll
            for (int i = 0; i < 4; ++i) {
                int it = tid + 256 * i;
                int r = it >> 3, c4 = it & 7;
                const float* src;
                if (qrows) {
                    int gr = row0 + r;
                    src = X + (size_t)(gr >> 2) * 4096 + (size_t)(kc >> 2) * 512
                            + (size_t)(gr & 3) * 128 + (kc & 3) * 32 + c4 * 4;
                } else {
                    src = X + (size_t)(row0 + r) * 1024 + kc * 32 + c4 * 4;
                }
                cp_async16(abase + (r * A_STRIDE + c4 * 4) * 4, src);
            }
#pragma unroll
            for (int i = 0; i < 2; ++i) {
                int it = tid + 256 * i;
                int r = it >> 3, c4 = it & 7;
                cp_async16(bbase + (r * A_STRIDE + c4 * 4) * 4,
                           B_all + (size_t)r * 1024 + kc * 32 + c4 * 4);
            }
            CP_COMMIT();
        };

        float acc[2][4][4];
#pragma unroll
        for (int t = 0; t < 2; ++t)
#pragma unroll
            for (int n = 0; n < 4; ++n)
#pragma unroll
                for (int e = 0; e < 4; ++e) acc[t][n][e] = 0.f;

        load_stage(0, 0);

        for (int kc = 0; kc < 32; ++kc) {
            int s = kc & 1;
            if (kc + 1 < 32) {
                load_stage(s ^ 1, kc + 1);
                asm volatile("cp.async.wait_group 1;" ::: "memory");
            } else {
                asm volatile("cp.async.wait_group 0;" ::: "memory");
            }
            __syncthreads();

            const float* A_sh = sm + s * (STAGE_BYTES / 4);
            const float* B_sh = A_sh + (A_BYTES / 4);
#pragma unroll
            for (int k0 = 0; k0 < 32; k0 += 8) {
                uint32_t a[2][4];
#pragma unroll
                for (int t = 0; t < 2; ++t) {
                    int ar = wm * 32 + t * 16;
                    const float* p0 = A_sh + (ar + gid) * A_STRIDE + k0 + tig;
                    const float* p1 = A_sh + (ar + gid + 8) * A_STRIDE + k0 + tig;
                    a[t][0] = tf32_bits(p0[0]);
                    a[t][1] = tf32_bits(p1[0]);
                    a[t][2] = tf32_bits(p0[4]);
                    a[t][3] = tf32_bits(p1[4]);
                }
                uint32_t b[4][2];
#pragma unroll
                for (int n = 0; n < 4; ++n) {
                    const float* p = B_sh + (wn * 32 + n * 8 + gid) * A_STRIDE + k0 + tig;
                    b[n][0] = __float_as_uint(p[0]);
                    b[n][1] = __float_as_uint(p[4]);
                }
#pragma unroll
                for (int t = 0; t < 2; ++t)
#pragma unroll
                    for (int n = 0; n < 4; ++n)
                        MMA_TF32(acc[t][n], a[t], b[n]);
            }
            __syncthreads();
        }

#pragma unroll
        for (int t = 0; t < 2; ++t) {
#pragma unroll
            for (int half = 0; half < 2; ++half) {
                int row = wm * 32 + t * 16 + gid + half * 8;
                int gr = row0 + row;
                float* op = (mode == 0)
                    ? out + (size_t)(gr >> 2) * 512 + (size_t)(gr & 3) * 128 + 64
                    : out + (size_t)N * 512 + (size_t)gr * 128 + 64;
#pragma unroll
                for (int n = 0; n < 4; ++n) {
                    int col = wn * 32 + n * 8 + 2 * tig;
                    float2 vv;
                    vv.x = acc[t][n][half * 2 + 0];
                    vv.y = acc[t][n][half * 2 + 1];
                    *(float2*)(op + col) = vv;
                }
            }
        }
    } else {
        // ================= v-weights + norm path =================
        const int b0 = (blk - 320) * 128;

        auto load_stage_v = [&](int s, int kc) {
            int gg = kc >> 2, sub = kc & 3;
            uint32_t abase = sbase + s * STAGE_BYTES;
            uint32_t bbase = abase + A_BYTES;
#pragma unroll
            for (int i = 0; i < 4; ++i) {
                int it = tid + 256 * i;
                int r = it >> 3, c4 = it & 7;
                cp_async16(abase + (r * A_STRIDE + c4 * 4) * 4,
                           v + (size_t)(b0 + r) * 1024 + gg * 128 + sub * 32 + c4 * 4);
            }
            if (tid < 128) {
                int r = tid >> 3, c4 = tid & 7;
                cp_async16(bbase + (r * A_STRIDE + c4 * 4) * 4,
                           B_v + (size_t)(gg * 16 + r) * 128 + sub * 32 + c4 * 4);
            }
            CP_COMMIT();
        };

        float acc[2][4];
        float sq[2][2];
#pragma unroll
        for (int t = 0; t < 2; ++t) {
#pragma unroll
            for (int e = 0; e < 4; ++e) acc[t][e] = 0.f;
            sq[t][0] = sq[t][1] = 0.f;
        }

        load_stage_v(0, 0);

        for (int kc = 0; kc < 32; ++kc) {
            int s = kc & 1;
            if (kc + 1 < 32) {
                load_stage_v(s ^ 1, kc + 1);
                asm volatile("cp.async.wait_group 1;" ::: "memory");
            } else {
                asm volatile("cp.async.wait_group 0;" ::: "memory");
            }
            __syncthreads();

            const float* A_sh = sm + s * (STAGE_BYTES / 4);
            const float* B_sh = A_sh + (A_BYTES / 4);
#pragma unroll
            for (int k0 = 0; k0 < 32; k0 += 8) {
                uint32_t a[2][4];
#pragma unroll
                for (int t = 0; t < 2; ++t) {
                    int ar = wm * 32 + t * 16;
                    const float* p0 = A_sh + (ar + gid) * A_STRIDE + k0 + tig;
                    const float* p1 = A_sh + (ar + gid + 8) * A_STRIDE + k0 + tig;
                    a[t][0] = tf32_bits(p0[0]);
                    a[t][1] = tf32_bits(p1[0]);
                    a[t][2] = tf32_bits(p0[4]);
                    a[t][3] = tf32_bits(p1[4]);
                }
                uint32_t b[2];
                {
                    const float* p = B_sh + (wn * 8 + gid) * A_STRIDE + k0 + tig;
                    b[0] = __float_as_uint(p[0]);
                    b[1] = __float_as_uint(p[4]);
                }
#pragma unroll
                for (int t = 0; t < 2; ++t)
                    MMA_TF32(acc[t], a[t], b);
            }
            __syncthreads();
            if ((kc & 3) == 3) {   // end of this gg: fold squares, reset
#pragma unroll
                for (int t = 0; t < 2; ++t) {
                    sq[t][0] += acc[t][0] * acc[t][0] + acc[t][1] * acc[t][1];
                    sq[t][1] += acc[t][2] * acc[t][2] + acc[t][3] * acc[t][3];
#pragma unroll
                    for (int e = 0; e < 4; ++e) acc[t][e] = 0.f;
                }
            }
        }

        // norm epilogue: pair-fold over tig (both cols of partner share j)
        const int j = wn * 2 + (tig >> 1);
#pragma unroll
        for (int t = 0; t < 2; ++t) {
#pragma unroll
            for (int half = 0; half < 2; ++half) {
                float s = sq[t][half];
                s += __shfl_xor_sync(0xffffffffu, s, 1);
                if ((tig & 1) == 0) {
                    int row = wm * 32 + t * 16 + gid + half * 8;
                    out[(size_t)N * 640 + (size_t)(b0 + row) * 4 + j] = sqrtf(s);
                }
            }
        }
    }
}

// ---------------------------------------------------------------------------
extern "C" void kernel_launch(void* const* d_in, const int* in_sizes, int n_in,
                              void* d_out, int out_size)
{
    const float* q      = (const float*)d_in[0];
    const float* k      = (const float*)d_in[1];
    const float* v      = (const float*)d_in[2];
    const float* q_orig = (const float*)d_in[3];
    const float* k_orig = (const float*)d_in[4];
    const float* qk_w   = (const float*)d_in[5];
    const float* W      = (const float*)d_in[6];
    const float* vt     = (const float*)d_in[7];
    float* out = (float*)d_out;
    const int N = in_sizes[0] / (32 * 128);   // 8192

    cudaFuncSetAttribute(gemm_kernel,
                         cudaFuncAttributeMaxDynamicSharedMemorySize, GEMM_SMEM);

    // persistent side stream + events for fork/join inside graph capture
    static cudaStream_t s1 = nullptr;
    static cudaEvent_t e_fork = nullptr, e_join = nullptr;
    if (!s1) {
        cudaStreamCreateWithFlags(&s1, cudaStreamNonBlocking);
        cudaEventCreateWithFlags(&e_fork, cudaEventDisableTiming);
        cudaEventCreateWithFlags(&e_join, cudaEventDisableTiming);
    }

    bool forked = (s1 != nullptr) &&
                  (cudaEventRecord(e_fork, 0) == cudaSuccess) &&
                  (cudaStreamWaitEvent(s1, e_fork, 0) == cudaSuccess);

    if (forked) {
        // rope (DRAM-heavy) on side stream, build+gemm on main stream — overlap
        rope_kernel<<<N, 160, 0, s1>>>(q, k, qk_w, out, N);
        build_B_kernel<<<320, 256>>>(qk_w, W, vt);
        gemm_kernel<<<384, 256, GEMM_SMEM>>>(q_orig, k_orig, v, out, N);
        cudaEventRecord(e_join, s1);
        cudaStreamWaitEvent(0, e_join, 0);
    } else {
        build_B_kernel<<<320, 256>>>(qk_w, W, vt);
        rope_kernel<<<N, 160>>>(q, k, qk_w, out, N);
        gemm_kernel<<<384, 256, GEMM_SMEM>>>(q_orig, k_orig, v, out, N);
    }
}

// round 13
// speedup vs baseline: 3.5787x; 1.0114x over previous
#include <cuda_runtime.h>
#include <stdint.h>
#include <math.h>

// ===========================================================================
// B_all[64][1024] : composed nope map (index cols 64..127). tf32-rounded.
// B_v[128][128]   : v-weights map, row = gg*16 + j*4 + r, col = d. tf32-rounded.
// w0c[512]        : compact rope weights, [n2][c] = qk_w[n2][c][0].
// ===========================================================================
__device__ float B_all[64 * 1024];
__device__ float B_v[128 * 128];
__device__ float w0c[512];

__device__ __forceinline__ float to_tf32(float x) {
    float r; asm("cvt.rna.tf32.f32 %0, %1;" : "=f"(r) : "f"(x)); return r;
}
__device__ __forceinline__ uint32_t tf32_bits(float x) {
    float r; asm("cvt.rna.tf32.f32 %0, %1;" : "=f"(r) : "f"(x));
    return __float_as_uint(r);
}
__device__ __forceinline__ uint32_t smem_u32(const void* p) {
    uint32_t a;
    asm("{ .reg .u64 t; cvta.to.shared.u64 t, %1; cvt.u32.u64 %0, t; }" : "=r"(a) : "l"(p));
    return a;
}
__device__ __forceinline__ void cp_async16(uint32_t dst, const void* src) {
    asm volatile("cp.async.cg.shared.global [%0], [%1], 16;"
                 :: "r"(dst), "l"(src) : "memory");
}
#define CP_COMMIT() asm volatile("cp.async.commit_group;" ::: "memory")

#define MMA_TF32(c, a, b) \
    asm volatile( \
        "mma.sync.aligned.m16n8k8.row.col.f32.tf32.tf32.f32 " \
        "{%0,%1,%2,%3}, {%4,%5,%6,%7}, {%8,%9}, {%0,%1,%2,%3};" \
        : "+f"((c)[0]), "+f"((c)[1]), "+f"((c)[2]), "+f"((c)[3]) \
        : "r"((a)[0]), "r"((a)[1]), "r"((a)[2]), "r"((a)[3]), \
          "r"((b)[0]), "r"((b)[1]))

// ---------------------------------------------------------------------------
// w0 prep: compact the r=0 column of qk_w (one-time, 512 scattered loads).
// ---------------------------------------------------------------------------
__global__ __launch_bounds__(256) void w0_prep_kernel(const float* __restrict__ qk_w)
{
    int i = blockIdx.x * 256 + threadIdx.x;   // 512 total
    w0c[i] = __ldg(qk_w + (i >> 4) * 256 + (i & 15) * 16);
}

// ---------------------------------------------------------------------------
// Build B_all + B_v: 320 blocks x 256 threads, one element per thread.
// ---------------------------------------------------------------------------
__global__ __launch_bounds__(256) void build_B_kernel(
    const float* __restrict__ qk_w,   // [32][16][16]
    const float* __restrict__ W,      // [64][960]
    const float* __restrict__ vt)     // [32][128][4]
{
    int e = blockIdx.x * 256 + threadIdx.x;   // 81920 total
    if (e < 65536) {
        int o = e >> 10, kk = e & 1023;
        int g = kk >> 7, dfull = kk & 127;
        int part = dfull >> 6, d = dfull & 63;
        int f = d & 1, p = (d >> 1) & 1, m = d >> 2;
        int n2 = f * 16 + m;
        const float* wrow = W + o * 960 + part * 480 + n2 * 15;
        const float* qrow = qk_w + n2 * 256 + (p * 8 + g) * 16;
        float acc = 0.f;
#pragma unroll
        for (int r = 1; r < 16; ++r)
            acc += __ldg(wrow + r - 1) * __ldg(qrow + r);
        B_all[e] = to_tf32(acc);
    } else {
        int e2 = e - 65536;                   // 0..16383
        int row = e2 >> 7, d = e2 & 127;      // row = gg*16 + j*4 + r
        int gg = row >> 4, j = (row >> 2) & 3, r = row & 3;
        B_v[e2] = to_tf32(__ldg(vt + (size_t)(gg * 4 + j) * 512 + d * 4 + r));
    }
}

// ---------------------------------------------------------------------------
// Rope path, register-only data: 2 tokens per block, 320 threads.
// Per token (160 threads): t<128 -> q outputs (j,part,m), t>=128 -> k outputs.
// Taps are .x/.y/.z/.w of 8 coalesced float4 loads. Weights from compact w0c.
// ---------------------------------------------------------------------------
__global__ __launch_bounds__(320) void rope_kernel(
    const float* __restrict__ q,      // [N,32,128]
    const float* __restrict__ k,      // [N,8,128]
    float* __restrict__ out, int N)
{
    __shared__ float w0[512];         // [n2][c]
    const int tid = threadIdx.x;
    if (tid < 256) {
        ((float2*)w0)[tid] = ((const float2*)w0c)[tid];
    }
    __syncthreads();

    const int b = blockIdx.x * 2 + (tid >= 160);
    const int t = (tid >= 160) ? tid - 160 : tid;

    if (t < 128) {
        const int j = t >> 5, part = (t >> 4) & 1, m = t & 15;
        const float* wA = w0 + m * 16;
        const float* wB = w0 + (16 + m) * 16;
        const float* base = q + (size_t)b * 4096 + j * 128 + part * 64 + m * 4;
        float acc0 = 0.f, acc1 = 0.f;
#pragma unroll
        for (int g = 0; g < 8; ++g) {
            float4 f = *(const float4*)(base + g * 512);
            acc0 += wA[g] * f.x + wA[8 + g] * f.z;
            acc1 += wB[g] * f.y + wB[8 + g] * f.w;
        }
        float* op = out + (size_t)b * 512 + j * 128 + part * 32 + m;
        op[0]  = acc0;
        op[16] = acc1;
    } else {
        const int tt = t - 128;
        const int part = tt >> 4, m = tt & 15;
        const float* wA = w0 + m * 16;
        const float* wB = w0 + (16 + m) * 16;
        const float* base = k + (size_t)b * 1024 + part * 64 + m * 4;
        float acc0 = 0.f, acc1 = 0.f;
#pragma unroll
        for (int g = 0; g < 8; ++g) {
            float4 f = *(const float4*)(base + g * 128);
            acc0 += wA[g] * f.x + wA[8 + g] * f.z;
            acc1 += wB[g] * f.y + wB[8 + g] * f.w;
        }
        float* op = out + (size_t)N * 512 + (size_t)b * 128 + part * 32 + m;
        op[0]  = acc0;
        op[16] = acc1;
    }
}

// ---------------------------------------------------------------------------
// Fused GEMM (tf32 mma.sync), 2-stage cp.async pipeline, 3 blocks/SM. 384 blks:
//  blk [0,256)   : A = q_orig (rows (b,j)), B_all, out cols 64..127
//  blk [256,320) : A = k_orig (rows b),     B_all, out cols 64..127
//  blk [320,384) : A = v (128 tokens), block-diagonal B_v (K=128 per gg),
//                  norm computed in epilogue -> weights
// ---------------------------------------------------------------------------
static constexpr int A_STRIDE = 36;                    // floats
static constexpr int A_BYTES = 128 * A_STRIDE * 4;     // 18432
static constexpr int STAGE_BYTES = A_BYTES + 64 * A_STRIDE * 4;  // 27648
static constexpr int GEMM_SMEM = 2 * STAGE_BYTES;      // 55296

__global__ __launch_bounds__(256, 3) void gemm_kernel(
    const float* __restrict__ q_orig, const float* __restrict__ k_orig,
    const float* __restrict__ v,
    float* __restrict__ out, int N)
{
    extern __shared__ float sm[];
    const uint32_t sbase = smem_u32(sm);

    const int tid = threadIdx.x;
    const int wid = tid >> 5;
    const int lane = tid & 31;
    const int gid = lane >> 2;
    const int tig = lane & 3;
    const int wm = wid >> 1;
    const int wn = wid & 1;
    const int blk = blockIdx.x;

    if (blk < 320) {
        // ================= q/k nope path =================
        const float* X;
        int row0, mode;
        if (blk < 256) { X = q_orig; row0 = blk * 128;         mode = 0; }
        else           { X = k_orig; row0 = (blk - 256) * 128; mode = 1; }
        const bool qrows = (mode == 0);

        auto load_stage = [&](int s, int kc) {
            uint32_t abase = sbase + s * STAGE_BYTES;
            uint32_t bbase = abase + A_BYTES;
#pragma unroll
            for (int i = 0; i < 4; ++i) {
                int it = tid + 256 * i;
                int r = it >> 3, c4 = it & 7;
                const float* src;
                if (qrows) {
                    int gr = row0 + r;
                    src = X + (size_t)(gr >> 2) * 4096 + (size_t)(kc >> 2) * 512
                            + (size_t)(gr & 3) * 128 + (kc & 3) * 32 + c4 * 4;
                } else {
                    src = X + (size_t)(row0 + r) * 1024 + kc * 32 + c4 * 4;
                }
                cp_async16(abase + (r * A_STRIDE + c4 * 4) * 4, src);
            }
#pragma unroll
            for (int i = 0; i < 2; ++i) {
                int it = tid + 256 * i;
                int r = it >> 3, c4 = it & 7;
                cp_async16(bbase + (r * A_STRIDE + c4 * 4) * 4,
                           B_all + (size_t)r * 1024 + kc * 32 + c4 * 4);
            }
            CP_COMMIT();
        };

        float acc[2][4][4];
#pragma unroll
        for (int t = 0; t < 2; ++t)
#pragma unroll
            for (int n = 0; n < 4; ++n)
#pragma unroll
                for (int e = 0; e < 4; ++e) acc[t][n][e] = 0.f;

        load_stage(0, 0);

        for (int kc = 0; kc < 32; ++kc) {
            int s = kc & 1;
            if (kc + 1 < 32) {
                load_stage(s ^ 1, kc + 1);
                asm volatile("cp.async.wait_group 1;" ::: "memory");
            } else {
                asm volatile("cp.async.wait_group 0;" ::: "memory");
            }
            __syncthreads();

            const float* A_sh = sm + s * (STAGE_BYTES / 4);
            const float* B_sh = A_sh + (A_BYTES / 4);
#pragma unroll
            for (int k0 = 0; k0 < 32; k0 += 8) {
                uint32_t a[2][4];
#pragma unroll
                for (int t = 0; t < 2; ++t) {
                    int ar = wm * 32 + t * 16;
                    const float* p0 = A_sh + (ar + gid) * A_STRIDE + k0 + tig;
                    const float* p1 = A_sh + (ar + gid + 8) * A_STRIDE + k0 + tig;
                    a[t][0] = tf32_bits(p0[0]);
                    a[t][1] = tf32_bits(p1[0]);
                    a[t][2] = tf32_bits(p0[4]);
                    a[t][3] = tf32_bits(p1[4]);
                }
                uint32_t b[4][2];
#pragma unroll
                for (int n = 0; n < 4; ++n) {
                    const float* p = B_sh + (wn * 32 + n * 8 + gid) * A_STRIDE + k0 + tig;
                    b[n][0] = __float_as_uint(p[0]);
                    b[n][1] = __float_as_uint(p[4]);
                }
#pragma unroll
                for (int t = 0; t < 2; ++t)
#pragma unroll
                    for (int n = 0; n < 4; ++n)
                        MMA_TF32(acc[t][n], a[t], b[n]);
            }
            __syncthreads();
        }

#pragma unroll
        for (int t = 0; t < 2; ++t) {
#pragma unroll
            for (int half = 0; half < 2; ++half) {
                int row = wm * 32 + t * 16 + gid + half * 8;
                int gr = row0 + row;
                float* op = (mode == 0)
                    ? out + (size_t)(gr >> 2) * 512 + (size_t)(gr & 3) * 128 + 64
                    : out + (size_t)N * 512 + (size_t)gr * 128 + 64;
#pragma unroll
                for (int n = 0; n < 4; ++n) {
                    int col = wn * 32 + n * 8 + 2 * tig;
                    float2 vv;
                    vv.x = acc[t][n][half * 2 + 0];
                    vv.y = acc[t][n][half * 2 + 1];
                    *(float2*)(op + col) = vv;
                }
            }
        }
    } else {
        // ================= v-weights + norm path =================
        const int b0 = (blk - 320) * 128;

        auto load_stage_v = [&](int s, int kc) {
            int gg = kc >> 2, sub = kc & 3;
            uint32_t abase = sbase + s * STAGE_BYTES;
            uint32_t bbase = abase + A_BYTES;
#pragma unroll
            for (int i = 0; i < 4; ++i) {
                int it = tid + 256 * i;
                int r = it >> 3, c4 = it & 7;
                cp_async16(abase + (r * A_STRIDE + c4 * 4) * 4,
                           v + (size_t)(b0 + r) * 1024 + gg * 128 + sub * 32 + c4 * 4);
            }
            if (tid < 128) {
                int r = tid >> 3, c4 = tid & 7;
                cp_async16(bbase + (r * A_STRIDE + c4 * 4) * 4,
                           B_v + (size_t)(gg * 16 + r) * 128 + sub * 32 + c4 * 4);
            }
            CP_COMMIT();
        };

        float acc[2][4];
        float sq[2][2];
#pragma unroll
        for (int t = 0; t < 2; ++t) {
#pragma unroll
            for (int e = 0; e < 4; ++e) acc[t][e] = 0.f;
            sq[t][0] = sq[t][1] = 0.f;
        }

        load_stage_v(0, 0);

        for (int kc = 0; kc < 32; ++kc) {
            int s = kc & 1;
            if (kc + 1 < 32) {
                load_stage_v(s ^ 1, kc + 1);
                asm volatile("cp.async.wait_group 1;" ::: "memory");
            } else {
                asm volatile("cp.async.wait_group 0;" ::: "memory");
            }
            __syncthreads();

            const float* A_sh = sm + s * (STAGE_BYTES / 4);
            const float* B_sh = A_sh + (A_BYTES / 4);
#pragma unroll
            for (int k0 = 0; k0 < 32; k0 += 8) {
                uint32_t a[2][4];
#pragma unroll
                for (int t = 0; t < 2; ++t) {
                    int ar = wm * 32 + t * 16;
                    const float* p0 = A_sh + (ar + gid) * A_STRIDE + k0 + tig;
                    const float* p1 = A_sh + (ar + gid + 8) * A_STRIDE + k0 + tig;
                    a[t][0] = tf32_bits(p0[0]);
                    a[t][1] = tf32_bits(p1[0]);
                    a[t][2] = tf32_bits(p0[4]);
                    a[t][3] = tf32_bits(p1[4]);
                }
                uint32_t b[2];
                {
                    const float* p = B_sh + (wn * 8 + gid) * A_STRIDE + k0 + tig;
                    b[0] = __float_as_uint(p[0]);
                    b[1] = __float_as_uint(p[4]);
                }
#pragma unroll
                for (int t = 0; t < 2; ++t)
                    MMA_TF32(acc[t], a[t], b);
            }
            __syncthreads();
            if ((kc & 3) == 3) {   // end of this gg: fold squares, reset
#pragma unroll
                for (int t = 0; t < 2; ++t) {
                    sq[t][0] += acc[t][0] * acc[t][0] + acc[t][1] * acc[t][1];
                    sq[t][1] += acc[t][2] * acc[t][2] + acc[t][3] * acc[t][3];
#pragma unroll
                    for (int e = 0; e < 4; ++e) acc[t][e] = 0.f;
                }
            }
        }

        // norm epilogue: pair-fold over tig (both cols of partner share j)
        const int j = wn * 2 + (tig >> 1);
#pragma unroll
        for (int t = 0; t < 2; ++t) {
#pragma unroll
            for (int half = 0; half < 2; ++half) {
                float s = sq[t][half];
                s += __shfl_xor_sync(0xffffffffu, s, 1);
                if ((tig & 1) == 0) {
                    int row = wm * 32 + t * 16 + gid + half * 8;
                    out[(size_t)N * 640 + (size_t)(b0 + row) * 4 + j] = sqrtf(s);
                }
            }
        }
    }
}

// ---------------------------------------------------------------------------
extern "C" void kernel_launch(void* const* d_in, const int* in_sizes, int n_in,
                              void* d_out, int out_size)
{
    const float* q      = (const float*)d_in[0];
    const float* k      = (const float*)d_in[1];
    const float* v      = (const float*)d_in[2];
    const float* q_orig = (const float*)d_in[3];
    const float* k_orig = (const float*)d_in[4];
    const float* qk_w   = (const float*)d_in[5];
    const float* W      = (const float*)d_in[6];
    const float* vt     = (const float*)d_in[7];
    float* out = (float*)d_out;
    const int N = in_sizes[0] / (32 * 128);   // 8192

    cudaFuncSetAttribute(gemm_kernel,
                         cudaFuncAttributeMaxDynamicSharedMemorySize, GEMM_SMEM);

    // persistent side stream + events for fork/join inside graph capture
    static cudaStream_t s1 = nullptr;
    static cudaEvent_t e_fork = nullptr, e_join = nullptr;
    if (!s1) {
        cudaStreamCreateWithFlags(&s1, cudaStreamNonBlocking);
        cudaEventCreateWithFlags(&e_fork, cudaEventDisableTiming);
        cudaEventCreateWithFlags(&e_join, cudaEventDisableTiming);
    }

    bool forked = (s1 != nullptr) &&
                  (cudaEventRecord(e_fork, 0) == cudaSuccess) &&
                  (cudaStreamWaitEvent(s1, e_fork, 0) == cudaSuccess);

    if (forked) {
        // rope (DRAM-heavy) on side stream, build+gemm on main stream — overlap
        w0_prep_kernel<<<2, 256, 0, s1>>>(qk_w);
        rope_kernel<<<N / 2, 320, 0, s1>>>(q, k, out, N);
        build_B_kernel<<<320, 256>>>(qk_w, W, vt);
        gemm_kernel<<<384, 256, GEMM_SMEM>>>(q_orig, k_orig, v, out, N);
        cudaEventRecord(e_join, s1);
        cudaStreamWaitEvent(0, e_join, 0);
    } else {
        w0_prep_kernel<<<2, 256>>>(qk_w);
        build_B_kernel<<<320, 256>>>(qk_w, W, vt);
        rope_kernel<<<N / 2, 320>>>(q, k, out, N);
        gemm_kernel<<<384, 256, GEMM_SMEM>>>(q_orig, k_orig, v, out, N);
    }
}

// round 15
// speedup vs baseline: 4.4212x; 1.2354x over previous
#include <cuda_runtime.h>
#include <stdint.h>
#include <math.h>

// ===========================================================================
// B_all[64][1024] : composed nope map (index cols 64..127). tf32-rounded.
// B_v[128][128]   : v-weights map, row = gg*16 + j*4 + r, col = d. tf32-rounded.
// w0c[512]        : compact rope weights, [n2][c] = qk_w[n2][c][0].
// ===========================================================================
__device__ float B_all[64 * 1024];
__device__ float B_v[128 * 128];
__device__ float w0c[512];

__device__ __forceinline__ float to_tf32(float x) {
    float r; asm("cvt.rna.tf32.f32 %0, %1;" : "=f"(r) : "f"(x)); return r;
}
__device__ __forceinline__ uint32_t tf32_bits(float x) {
    float r; asm("cvt.rna.tf32.f32 %0, %1;" : "=f"(r) : "f"(x));
    return __float_as_uint(r);
}
__device__ __forceinline__ uint32_t smem_u32(const void* p) {
    uint32_t a;
    asm("{ .reg .u64 t; cvta.to.shared.u64 t, %1; cvt.u32.u64 %0, t; }" : "=r"(a) : "l"(p));
    return a;
}
__device__ __forceinline__ void cp_async16(uint32_t dst, const void* src) {
    asm volatile("cp.async.cg.shared.global [%0], [%1], 16;"
                 :: "r"(dst), "l"(src) : "memory");
}
#define CP_COMMIT() asm volatile("cp.async.commit_group;" ::: "memory")

#define MMA_TF32(c, a, b) \
    asm volatile( \
        "mma.sync.aligned.m16n8k8.row.col.f32.tf32.tf32.f32 " \
        "{%0,%1,%2,%3}, {%4,%5,%6,%7}, {%8,%9}, {%0,%1,%2,%3};" \
        : "+f"((c)[0]), "+f"((c)[1]), "+f"((c)[2]), "+f"((c)[3]) \
        : "r"((a)[0]), "r"((a)[1]), "r"((a)[2]), "r"((a)[3]), \
          "r"((b)[0]), "r"((b)[1]))

// ---------------------------------------------------------------------------
// Build B_all + B_v + w0c: 322 blocks x 256 threads, one element per thread.
// ---------------------------------------------------------------------------
__global__ __launch_bounds__(256) void build_B_kernel(
    const float* __restrict__ qk_w,   // [32][16][16]
    const float* __restrict__ W,      // [64][960]
    const float* __restrict__ vt)     // [32][128][4]
{
    int e = blockIdx.x * 256 + threadIdx.x;
    if (e < 65536) {
        int o = e >> 10, kk = e & 1023;
        int g = kk >> 7, dfull = kk & 127;
        int part = dfull >> 6, d = dfull & 63;
        int f = d & 1, p = (d >> 1) & 1, m = d >> 2;
        int n2 = f * 16 + m;
        const float* wrow = W + o * 960 + part * 480 + n2 * 15;
        const float* qrow = qk_w + n2 * 256 + (p * 8 + g) * 16;
        float acc = 0.f;
#pragma unroll
        for (int r = 1; r < 16; ++r)
            acc += __ldg(wrow + r - 1) * __ldg(qrow + r);
        B_all[e] = to_tf32(acc);
    } else if (e < 81920) {
        int e2 = e - 65536;                   // 0..16383
        int row = e2 >> 7, d = e2 & 127;      // row = gg*16 + j*4 + r
        int gg = row >> 4, j = (row >> 2) & 3, r = row & 3;
        B_v[e2] = to_tf32(__ldg(vt + (size_t)(gg * 4 + j) * 512 + d * 4 + r));
    } else if (e < 82432) {
        int i = e - 81920;                    // 0..511
        w0c[i] = __ldg(qk_w + (i >> 4) * 256 + (i & 15) * 16);
    }
}

// ---------------------------------------------------------------------------
// Fused kernel: 4480 blocks x 256 threads.
//  blk [0,256)      : GEMM A = q_orig (rows (b,j)), B_all, out cols 64..127
//  blk [256,320)    : GEMM A = k_orig (rows b),     B_all, out cols 64..127
//  blk [320,384)    : GEMM A = v, block-diagonal B_v, norm -> weights
//  blk [384,4480)   : rope (2 tokens/block, 320 work-units over 256 thr x2)
// GEMM: tf32 mma.sync, 2-stage cp.async, M=128 N=64, K chunk 32.
// ---------------------------------------------------------------------------
static constexpr int A_STRIDE = 36;                    // floats
static constexpr int A_BYTES = 128 * A_STRIDE * 4;     // 18432
static constexpr int STAGE_BYTES = A_BYTES + 64 * A_STRIDE * 4;  // 27648
static constexpr int GEMM_SMEM = 2 * STAGE_BYTES;      // 55296

__global__ __launch_bounds__(256, 3) void fused_kernel(
    const float* __restrict__ q_orig, const float* __restrict__ k_orig,
    const float* __restrict__ v,
    const float* __restrict__ q, const float* __restrict__ kk_in,
    float* __restrict__ out, int N)
{
    extern __shared__ float sm[];
    const uint32_t sbase = smem_u32(sm);

    const int tid = threadIdx.x;
    const int blk = blockIdx.x;

    if (blk >= 384) {
        // ================= rope path (2 tokens per block) =================
        float* w0 = sm;               // [n2][c], 512 floats
        ((float2*)w0)[tid] = ((const float2*)w0c)[tid];
        __syncthreads();
        const int b0 = (blk - 384) * 2;
#pragma unroll
        for (int i = 0; i < 2; ++i) {
            int u = tid + 256 * i;
            if (u >= 320) break;
            const int b = b0 + (u >= 160);
            const int t = (u >= 160) ? u - 160 : u;
            if (t < 128) {
                const int j = t >> 5, part = (t >> 4) & 1, m = t & 15;
                const float* wA = w0 + m * 16;
                const float* wB = w0 + (16 + m) * 16;
                const float* base = q + (size_t)b * 4096 + j * 128 + part * 64 + m * 4;
                float acc0 = 0.f, acc1 = 0.f;
#pragma unroll
                for (int g = 0; g < 8; ++g) {
                    float4 f = *(const float4*)(base + g * 512);
                    acc0 += wA[g] * f.x + wA[8 + g] * f.z;
                    acc1 += wB[g] * f.y + wB[8 + g] * f.w;
                }
                float* op = out + (size_t)b * 512 + j * 128 + part * 32 + m;
                op[0]  = acc0;
                op[16] = acc1;
            } else {
                const int tt = t - 128;
                const int part = tt >> 4, m = tt & 15;
                const float* wA = w0 + m * 16;
                const float* wB = w0 + (16 + m) * 16;
                const float* base = kk_in + (size_t)b * 1024 + part * 64 + m * 4;
                float acc0 = 0.f, acc1 = 0.f;
#pragma unroll
                for (int g = 0; g < 8; ++g) {
                    float4 f = *(const float4*)(base + g * 128);
                    acc0 += wA[g] * f.x + wA[8 + g] * f.z;
                    acc1 += wB[g] * f.y + wB[8 + g] * f.w;
                }
                float* op = out + (size_t)N * 512 + (size_t)b * 128 + part * 32 + m;
                op[0]  = acc0;
                op[16] = acc1;
            }
        }
        return;
    }

    const int wid = tid >> 5;
    const int lane = tid & 31;
    const int gid = lane >> 2;
    const int tig = lane & 3;
    const int wm = wid >> 1;
    const int wn = wid & 1;

    if (blk < 320) {
        // ================= q/k nope path =================
        const float* X;
        int row0, mode;
        if (blk < 256) { X = q_orig; row0 = blk * 128;         mode = 0; }
        else           { X = k_orig; row0 = (blk - 256) * 128; mode = 1; }
        const bool qrows = (mode == 0);

        auto load_stage = [&](int s, int kc) {
            uint32_t abase = sbase + s * STAGE_BYTES;
            uint32_t bbase = abase + A_BYTES;
#pragma unroll
            for (int i = 0; i < 4; ++i) {
                int it = tid + 256 * i;
                int r = it >> 3, c4 = it & 7;
                const float* src;
                if (qrows) {
                    int gr = row0 + r;
                    src = X + (size_t)(gr >> 2) * 4096 + (size_t)(kc >> 2) * 512
                            + (size_t)(gr & 3) * 128 + (kc & 3) * 32 + c4 * 4;
                } else {
                    src = X + (size_t)(row0 + r) * 1024 + kc * 32 + c4 * 4;
                }
                cp_async16(abase + (r * A_STRIDE + c4 * 4) * 4, src);
            }
#pragma unroll
            for (int i = 0; i < 2; ++i) {
                int it = tid + 256 * i;
                int r = it >> 3, c4 = it & 7;
                cp_async16(bbase + (r * A_STRIDE + c4 * 4) * 4,
                           B_all + (size_t)r * 1024 + kc * 32 + c4 * 4);
            }
            CP_COMMIT();
        };

        float acc[2][4][4];
#pragma unroll
        for (int t = 0; t < 2; ++t)
#pragma unroll
            for (int n = 0; n < 4; ++n)
#pragma unroll
                for (int e = 0; e < 4; ++e) acc[t][n][e] = 0.f;

        load_stage(0, 0);

        for (int kc = 0; kc < 32; ++kc) {
            int s = kc & 1;
            if (kc + 1 < 32) {
                load_stage(s ^ 1, kc + 1);
                asm volatile("cp.async.wait_group 1;" ::: "memory");
            } else {
                asm volatile("cp.async.wait_group 0;" ::: "memory");
            }
            __syncthreads();

            const float* A_sh = sm + s * (STAGE_BYTES / 4);
            const float* B_sh = A_sh + (A_BYTES / 4);
#pragma unroll
            for (int k0 = 0; k0 < 32; k0 += 8) {
                uint32_t a[2][4];
#pragma unroll
                for (int t = 0; t < 2; ++t) {
                    int ar = wm * 32 + t * 16;
                    const float* p0 = A_sh + (ar + gid) * A_STRIDE + k0 + tig;
                    const float* p1 = A_sh + (ar + gid + 8) * A_STRIDE + k0 + tig;
                    a[t][0] = tf32_bits(p0[0]);
                    a[t][1] = tf32_bits(p1[0]);
                    a[t][2] = tf32_bits(p0[4]);
                    a[t][3] = tf32_bits(p1[4]);
                }
                uint32_t b[4][2];
#pragma unroll
                for (int n = 0; n < 4; ++n) {
                    const float* p = B_sh + (wn * 32 + n * 8 + gid) * A_STRIDE + k0 + tig;
                    b[n][0] = __float_as_uint(p[0]);
                    b[n][1] = __float_as_uint(p[4]);
                }
#pragma unroll
                for (int t = 0; t < 2; ++t)
#pragma unroll
                    for (int n = 0; n < 4; ++n)
                        MMA_TF32(acc[t][n], a[t], b[n]);
            }
            __syncthreads();
        }

#pragma unroll
        for (int t = 0; t < 2; ++t) {
#pragma unroll
            for (int half = 0; half < 2; ++half) {
                int row = wm * 32 + t * 16 + gid + half * 8;
                int gr = row0 + row;
                float* op = (mode == 0)
                    ? out + (size_t)(gr >> 2) * 512 + (size_t)(gr & 3) * 128 + 64
                    : out + (size_t)N * 512 + (size_t)gr * 128 + 64;
#pragma unroll
                for (int n = 0; n < 4; ++n) {
                    int col = wn * 32 + n * 8 + 2 * tig;
                    float2 vv;
                    vv.x = acc[t][n][half * 2 + 0];
                    vv.y = acc[t][n][half * 2 + 1];
                    *(float2*)(op + col) = vv;
                }
            }
        }
    } else {
        // ================= v-weights + norm path =================
        const int b0 = (blk - 320) * 128;

        auto load_stage_v = [&](int s, int kc) {
            int gg = kc >> 2, sub = kc & 3;
            uint32_t abase = sbase + s * STAGE_BYTES;
            uint32_t bbase = abase + A_BYTES;
#pragma unroll
            for (int i = 0; i < 4; ++i) {
                int it = tid + 256 * i;
                int r = it >> 3, c4 = it & 7;
                cp_async16(abase + (r * A_STRIDE + c4 * 4) * 4,
                           v + (size_t)(b0 + r) * 1024 + gg * 128 + sub * 32 + c4 * 4);
            }
            if (tid < 128) {
                int r = tid >> 3, c4 = tid & 7;
                cp_async16(bbase + (r * A_STRIDE + c4 * 4) * 4,
                           B_v + (size_t)(gg * 16 + r) * 128 + sub * 32 + c4 * 4);
            }
            CP_COMMIT();
        };

        float acc[2][4];
        float sq[2][2];
#pragma unroll
        for (int t = 0; t < 2; ++t) {
#pragma unroll
            for (int e = 0; e < 4; ++e) acc[t][e] = 0.f;
            sq[t][0] = sq[t][1] = 0.f;
        }

        load_stage_v(0, 0);

        for (int kc = 0; kc < 32; ++kc) {
            int s = kc & 1;
            if (kc + 1 < 32) {
                load_stage_v(s ^ 1, kc + 1);
                asm volatile("cp.async.wait_group 1;" ::: "memory");
            } else {
                asm volatile("cp.async.wait_group 0;" ::: "memory");
            }
            __syncthreads();

            const float* A_sh = sm + s * (STAGE_BYTES / 4);
            const float* B_sh = A_sh + (A_BYTES / 4);
#pragma unroll
            for (int k0 = 0; k0 < 32; k0 += 8) {
                uint32_t a[2][4];
#pragma unroll
                for (int t = 0; t < 2; ++t) {
                    int ar = wm * 32 + t * 16;
                    const float* p0 = A_sh + (ar + gid) * A_STRIDE + k0 + tig;
                    const float* p1 = A_sh + (ar + gid + 8) * A_STRIDE + k0 + tig;
                    a[t][0] = tf32_bits(p0[0]);
                    a[t][1] = tf32_bits(p1[0]);
                    a[t][2] = tf32_bits(p0[4]);
                    a[t][3] = tf32_bits(p1[4]);
                }
                uint32_t b[2];
                {
                    const float* p = B_sh + (wn * 8 + gid) * A_STRIDE + k0 + tig;
                    b[0] = __float_as_uint(p[0]);
                    b[1] = __float_as_uint(p[4]);
                }
#pragma unroll
                for (int t = 0; t < 2; ++t)
                    MMA_TF32(acc[t], a[t], b);
            }
            __syncthreads();
            if ((kc & 3) == 3) {   // end of this gg: fold squares, reset
#pragma unroll
                for (int t = 0; t < 2; ++t) {
                    sq[t][0] += acc[t][0] * acc[t][0] + acc[t][1] * acc[t][1];
                    sq[t][1] += acc[t][2] * acc[t][2] + acc[t][3] * acc[t][3];
#pragma unroll
                    for (int e = 0; e < 4; ++e) acc[t][e] = 0.f;
                }
            }
        }

        // norm epilogue: pair-fold over tig (both cols of partner share j)
        const int j = wn * 2 + (tig >> 1);
#pragma unroll
        for (int t = 0; t < 2; ++t) {
#pragma unroll
            for (int half = 0; half < 2; ++half) {
                float s = sq[t][half];
                s += __shfl_xor_sync(0xffffffffu, s, 1);
                if ((tig & 1) == 0) {
                    int row = wm * 32 + t * 16 + gid + half * 8;
                    out[(size_t)N * 640 + (size_t)(b0 + row) * 4 + j] = sqrtf(s);
                }
            }
        }
    }
}

// ---------------------------------------------------------------------------
extern "C" void kernel_launch(void* const* d_in, const int* in_sizes, int n_in,
                              void* d_out, int out_size)
{
    const float* q      = (const float*)d_in[0];
    const float* k      = (const float*)d_in[1];
    const float* v      = (const float*)d_in[2];
    const float* q_orig = (const float*)d_in[3];
    const float* k_orig = (const float*)d_in[4];
    const float* qk_w   = (const float*)d_in[5];
    const float* W      = (const float*)d_in[6];
    const float* vt     = (const float*)d_in[7];
    float* out = (float*)d_out;
    const int N = in_sizes[0] / (32 * 128);   // 8192

    cudaFuncSetAttribute(fused_kernel,
                         cudaFuncAttributeMaxDynamicSharedMemorySize, GEMM_SMEM);

    build_B_kernel<<<322, 256>>>(qk_w, W, vt);
    fused_kernel<<<384 + N / 2, 256, GEMM_SMEM>>>(q_orig, k_orig, v, q, k, out, N);
}